// round 6
// baseline (speedup 1.0000x reference)
#include <cuda_runtime.h>
#include <math.h>
#include <stdint.h>

#define BATCH 2
#define SEQ 2048
#define NH 16
#define HD 64
#define DM 1024
#define WINDOW 512
#define MTOT (BATCH*SEQ)      // 4096
#define NQKV (3*DM)           // 3072

// GEMM tiling: 128x128x16, 256 threads, warp tile 64x32, 4-stage cp.async
#define GBM 128
#define GBN 128
#define GBK 16
#define GAP 20     // A smem pitch
#define GBP 136    // B smem pitch
#define GSTAGES 4

// attention pitches
#define KP 68
#define VP 72

__device__ float g_qkv[(size_t)MTOT * NQKV];
__device__ float g_attn[(size_t)MTOT * DM];
__device__ float g_xc[(size_t)MTOT * DM];
__device__ float g_w1[(size_t)DM * NQKV];
__device__ float g_w2[(size_t)DM * DM];

__device__ __forceinline__ uint32_t f2tf32(float f) {
    uint32_t u;
    asm("cvt.rna.tf32.f32 %0, %1;" : "=r"(u) : "f"(f));
    return u;
}
__device__ __forceinline__ float ex2(float x) {
    float y;
    asm("ex2.approx.ftz.f32 %0, %1;" : "=f"(y) : "f"(x));
    return y;
}
__device__ __forceinline__ void mma_tf32(float c[4], const uint32_t a[4], const uint32_t b[2]) {
    asm volatile(
        "mma.sync.aligned.m16n8k8.row.col.f32.tf32.tf32.f32 "
        "{%0,%1,%2,%3}, {%4,%5,%6,%7}, {%8,%9}, {%0,%1,%2,%3};"
        : "+f"(c[0]), "+f"(c[1]), "+f"(c[2]), "+f"(c[3])
        : "r"(a[0]), "r"(a[1]), "r"(a[2]), "r"(a[3]), "r"(b[0]), "r"(b[1]));
}
__device__ __forceinline__ void cp_async16(void* dst, const void* src) {
    uint32_t s = (uint32_t)__cvta_generic_to_shared(dst);
    asm volatile("cp.async.ca.shared.global [%0], [%1], 16;" :: "r"(s), "l"(src));
}

// elementwise tf32 pre-round
__global__ __launch_bounds__(256) void cvt_tf32_kernel(const float* __restrict__ in,
                                                       float* __restrict__ outp, int n4)
{
    int idx = blockIdx.x * 256 + threadIdx.x;
    int stride = gridDim.x * 256;
    for (; idx < n4; idx += stride) {
        float4 v = reinterpret_cast<const float4*>(in)[idx];
        uint4 u;
        u.x = f2tf32(v.x); u.y = f2tf32(v.y); u.z = f2tf32(v.z); u.w = f2tf32(v.w);
        reinterpret_cast<uint4*>(outp)[idx] = u;
    }
}

// ---------------------------------------------------------------------------
// TF32 GEMM v4: 128x128x16 tile, 256 threads (8 warps, 2x4, warp tile 64x32),
// 4-stage cp.async ring, 2 CTAs/SM. Inputs pre-rounded to tf32.
// ---------------------------------------------------------------------------
template<int ROUND>
__global__ __launch_bounds__(256, 2) void tf32_gemm_bias(
    const float* __restrict__ A, const float* __restrict__ B,
    const float* __restrict__ bias, float* __restrict__ C,
    int M, int N, int K)
{
    extern __shared__ float gsm[];
    float* As = gsm;                          // [GSTAGES][128][GAP]
    float* Bs = gsm + GSTAGES * 128 * GAP;    // [GSTAGES][16][GBP]

    const int tid  = threadIdx.x;
    const int lane = tid & 31;
    const int warp = tid >> 5;
    const int wm = warp & 1;          // 0..1 (M)
    const int wn = warp >> 1;         // 0..3 (N)
    const int g  = lane >> 2;
    const int tg = lane & 3;

    const int rowBase = blockIdx.y * GBM;
    const int colBase = blockIdx.x * GBN;
    const int nkt = K / GBK;

    float acc[4][4][4];
#pragma unroll
    for (int i = 0; i < 4; i++)
#pragma unroll
        for (int j = 0; j < 4; j++)
#pragma unroll
            for (int c = 0; c < 4; c++) acc[i][j][c] = 0.f;

#define ISSUE(KT, ST)                                                          \
    {                                                                          \
        float* as_ = As + (ST) * (128 * GAP);                                  \
        float* bs_ = Bs + (ST) * (16 * GBP);                                   \
        _Pragma("unroll")                                                      \
        for (int f = 0; f < 2; f++) {                                          \
            int idx = tid + 256 * f;                                           \
            int arow = idx >> 2, acol = (idx & 3) * 4;                         \
            cp_async16(as_ + arow * GAP + acol,                                \
                       A + (size_t)(rowBase + arow) * K + (KT) * GBK + acol);  \
            int bk = idx >> 5, bn = (idx & 31) * 4;                            \
            cp_async16(bs_ + bk * GBP + bn,                                    \
                       B + (size_t)((KT) * GBK + bk) * N + colBase + bn);      \
        }                                                                      \
        asm volatile("cp.async.commit_group;");                                \
    }

    ISSUE(0, 0);
    ISSUE(1, 1);
    ISSUE(2, 2);

    for (int kt = 0; kt < nkt; kt++) {
        const int rem = nkt - 1 - kt;
        if (rem >= 2)      { asm volatile("cp.async.wait_group 2;"); }
        else if (rem == 1) { asm volatile("cp.async.wait_group 1;"); }
        else               { asm volatile("cp.async.wait_group 0;"); }
        __syncthreads();

        if (kt + 3 < nkt) ISSUE(kt + 3, (kt + 3) & 3);

        const float* as = As + (kt & 3) * (128 * GAP);
        const float* bs = Bs + (kt & 3) * (16 * GBP);

#pragma unroll
        for (int ks = 0; ks < 2; ks++) {
            const int kk = ks * 8;
            uint32_t af[4][4];
#pragma unroll
            for (int mi = 0; mi < 4; mi++) {
                const int m = wm * 64 + mi * 16;
                af[mi][0] = __float_as_uint(as[(m + g) * GAP + kk + tg]);
                af[mi][1] = __float_as_uint(as[(m + g + 8) * GAP + kk + tg]);
                af[mi][2] = __float_as_uint(as[(m + g) * GAP + kk + tg + 4]);
                af[mi][3] = __float_as_uint(as[(m + g + 8) * GAP + kk + tg + 4]);
            }
            uint32_t bf[4][2];
#pragma unroll
            for (int nj = 0; nj < 4; nj++) {
                const int n = wn * 32 + nj * 8;
                bf[nj][0] = __float_as_uint(bs[(kk + tg) * GBP + n + g]);
                bf[nj][1] = __float_as_uint(bs[(kk + tg + 4) * GBP + n + g]);
            }
#pragma unroll
            for (int mi = 0; mi < 4; mi++)
#pragma unroll
                for (int nj = 0; nj < 4; nj++)
                    mma_tf32(acc[mi][nj], af[mi], bf[nj]);
        }
    }
#undef ISSUE

#pragma unroll
    for (int mi = 0; mi < 4; mi++) {
#pragma unroll
        for (int nj = 0; nj < 4; nj++) {
            const int col = colBase + wn * 32 + nj * 8 + tg * 2;
            const float bx = bias[col];
            const float by = bias[col + 1];
            const size_t r0 = (size_t)(rowBase + wm * 64 + mi * 16 + g);
            const size_t r1 = r0 + 8;
            float v00 = acc[mi][nj][0] + bx, v01 = acc[mi][nj][1] + by;
            float v10 = acc[mi][nj][2] + bx, v11 = acc[mi][nj][3] + by;
            if (ROUND) {
                v00 = __uint_as_float(f2tf32(v00));
                v01 = __uint_as_float(f2tf32(v01));
                v10 = __uint_as_float(f2tf32(v10));
                v11 = __uint_as_float(f2tf32(v11));
            }
            float2 o0 = {v00, v01}, o1 = {v10, v11};
            *reinterpret_cast<float2*>(C + r0 * N + col) = o0;
            *reinterpret_cast<float2*>(C + r1 * N + col) = o1;
        }
    }
}

// ---------------------------------------------------------------------------
// Sliding-window attention, tf32 MMA (unchanged from round 5).
// ---------------------------------------------------------------------------
__global__ __launch_bounds__(128, 3) void swa_mma_kernel(const float* __restrict__ qkv,
                                                         float* __restrict__ outp)
{
    extern __shared__ float sm[];
    float* Qs = sm;                      // [64][KP]  (later reused as Ps)
    float* Ps = sm;
    float* Ks = Qs + 64 * KP;            // [2][64][KP]
    float* Vs = Ks + 2 * 64 * KP;        // [64][VP]

    const int tid  = threadIdx.x;
    const int lane = tid & 31;
    const int warp = tid >> 5;
    const int g  = lane >> 2;
    const int tg = lane & 3;
    const int bh = blockIdx.y;
    const int b = bh >> 4;
    const int h = bh & 15;
    const int qt = blockIdx.x;
    const int q0 = qt * 64;

    const float QSCALE = 0.125f * 1.4426950408889634f;

    const int r  = tid >> 1;
    const int c0 = (tid & 1) * 32;

#define PREFETCH_K(T, ST)                                                        \
    {                                                                            \
        const float* ksrc = qkv + (size_t)(b * SEQ + (T) * 64 + r) * NQKV        \
                            + DM + h * HD + c0;                                  \
        float* kd = Ks + (ST) * 64 * KP + r * KP + c0;                           \
        _Pragma("unroll")                                                        \
        for (int c = 0; c < 32; c += 4) cp_async16(kd + c, ksrc + c);            \
        asm volatile("cp.async.commit_group;");                                  \
    }
#define PREFETCH_V(T)                                                            \
    {                                                                            \
        const float* vsrc = qkv + (size_t)(b * SEQ + (T) * 64 + r) * NQKV        \
                            + 2 * DM + h * HD + c0;                              \
        float* vd = Vs + r * VP + c0;                                            \
        _Pragma("unroll")                                                        \
        for (int c = 0; c < 32; c += 4) cp_async16(vd + c, vsrc + c);            \
        asm volatile("cp.async.commit_group;");                                  \
    }

    {
        const float* src = qkv + (size_t)(b * SEQ + q0 + r) * NQKV + h * HD + c0;
#pragma unroll
        for (int c = 0; c < 32; c += 4) {
            float4 v = *reinterpret_cast<const float4*>(src + c);
            uint4 u;
            u.x = f2tf32(v.x * QSCALE); u.y = f2tf32(v.y * QSCALE);
            u.z = f2tf32(v.z * QSCALE); u.w = f2tf32(v.w * QSCALE);
            *reinterpret_cast<uint4*>(&Qs[r * KP + c0 + c]) = u;
        }
    }

    int kstart = q0 - (WINDOW - 1);
    if (kstart < 0) kstart = 0;
    const int t0 = kstart >> 6;

    PREFETCH_K(t0, t0 & 1);
    PREFETCH_V(t0);
    if (t0 < qt) PREFETCH_K(t0 + 1, (t0 + 1) & 1);

    __syncthreads();

    const int row0 = warp * 16 + g;
    uint32_t qf[8][4];
#pragma unroll
    for (int ks = 0; ks < 8; ks++) {
        const int kk = ks * 8;
        qf[ks][0] = __float_as_uint(Qs[row0 * KP + kk + tg]);
        qf[ks][1] = __float_as_uint(Qs[(row0 + 8) * KP + kk + tg]);
        qf[ks][2] = __float_as_uint(Qs[row0 * KP + kk + tg + 4]);
        qf[ks][3] = __float_as_uint(Qs[(row0 + 8) * KP + kk + tg + 4]);
    }

    float oacc[8][4];
#pragma unroll
    for (int nb = 0; nb < 8; nb++)
#pragma unroll
        for (int c = 0; c < 4; c++) oacc[nb][c] = 0.f;
    float m0 = -INFINITY, m1 = -INFINITY, l0 = 0.f, l1 = 0.f;

    const int qg0 = q0 + row0;
    const int qg1 = qg0 + 8;

    for (int t = t0; t <= qt; t++) {
        if (t < qt) { asm volatile("cp.async.wait_group 2;"); }
        else        { asm volatile("cp.async.wait_group 1;"); }
        __syncthreads();

        const float* ks_ = Ks + (t & 1) * 64 * KP;

        float sacc[8][4];
#pragma unroll
        for (int nb = 0; nb < 8; nb++)
#pragma unroll
            for (int c = 0; c < 4; c++) sacc[nb][c] = 0.f;

#pragma unroll
        for (int ks = 0; ks < 8; ks++) {
            const int kk = ks * 8;
#pragma unroll
            for (int nb = 0; nb < 8; nb++) {
                uint32_t bf[2];
                bf[0] = __float_as_uint(ks_[(nb * 8 + g) * KP + kk + tg]);
                bf[1] = __float_as_uint(ks_[(nb * 8 + g) * KP + kk + tg + 4]);
                mma_tf32(sacc[nb], qf[ks], bf);
            }
        }

        const int delta = q0 - t * 64;
        if (delta == 0 || delta == WINDOW) {
#pragma unroll
            for (int nb = 0; nb < 8; nb++) {
                const int kg0 = t * 64 + nb * 8 + tg * 2;
                const int kg1 = kg0 + 1;
                int d;
                d = qg0 - kg0; if (d < 0 || d >= WINDOW) sacc[nb][0] = -INFINITY;
                d = qg0 - kg1; if (d < 0 || d >= WINDOW) sacc[nb][1] = -INFINITY;
                d = qg1 - kg0; if (d < 0 || d >= WINDOW) sacc[nb][2] = -INFINITY;
                d = qg1 - kg1; if (d < 0 || d >= WINDOW) sacc[nb][3] = -INFINITY;
            }
        }

        float mx0 = -INFINITY, mx1 = -INFINITY;
#pragma unroll
        for (int nb = 0; nb < 8; nb++) {
            mx0 = fmaxf(mx0, fmaxf(sacc[nb][0], sacc[nb][1]));
            mx1 = fmaxf(mx1, fmaxf(sacc[nb][2], sacc[nb][3]));
        }
        mx0 = fmaxf(mx0, __shfl_xor_sync(0xffffffffu, mx0, 1));
        mx0 = fmaxf(mx0, __shfl_xor_sync(0xffffffffu, mx0, 2));
        mx1 = fmaxf(mx1, __shfl_xor_sync(0xffffffffu, mx1, 1));
        mx1 = fmaxf(mx1, __shfl_xor_sync(0xffffffffu, mx1, 2));

        const float mn0 = fmaxf(m0, mx0), mn1 = fmaxf(m1, mx1);
        const float md0 = (mn0 == -INFINITY) ? 0.f : mn0;
        const float md1 = (mn1 == -INFINITY) ? 0.f : mn1;
        const float sc0 = ex2(m0 - md0);
        const float sc1 = ex2(m1 - md1);

        float ps0 = 0.f, ps1 = 0.f;
#pragma unroll
        for (int nb = 0; nb < 8; nb++) {
            float p00 = ex2(sacc[nb][0] - md0);
            float p01 = ex2(sacc[nb][1] - md0);
            float p10 = ex2(sacc[nb][2] - md1);
            float p11 = ex2(sacc[nb][3] - md1);
            ps0 += p00 + p01;
            ps1 += p10 + p11;
            uint2 u0, u1;
            u0.x = f2tf32(p00); u0.y = f2tf32(p01);
            u1.x = f2tf32(p10); u1.y = f2tf32(p11);
            *reinterpret_cast<uint2*>(&Ps[row0 * KP + nb * 8 + tg * 2]) = u0;
            *reinterpret_cast<uint2*>(&Ps[(row0 + 8) * KP + nb * 8 + tg * 2]) = u1;
        }
        ps0 += __shfl_xor_sync(0xffffffffu, ps0, 1);
        ps0 += __shfl_xor_sync(0xffffffffu, ps0, 2);
        ps1 += __shfl_xor_sync(0xffffffffu, ps1, 1);
        ps1 += __shfl_xor_sync(0xffffffffu, ps1, 2);

        l0 = l0 * sc0 + ps0;
        l1 = l1 * sc1 + ps1;
        m0 = mn0; m1 = mn1;
#pragma unroll
        for (int nb = 0; nb < 8; nb++) {
            oacc[nb][0] *= sc0; oacc[nb][1] *= sc0;
            oacc[nb][2] *= sc1; oacc[nb][3] *= sc1;
        }

        if (t < qt) { asm volatile("cp.async.wait_group 1;"); }
        else        { asm volatile("cp.async.wait_group 0;"); }
        __syncwarp();

#pragma unroll
        for (int ks = 0; ks < 8; ks++) {
            const int kk = ks * 8;
            uint32_t af[4];
            af[0] = __float_as_uint(Ps[row0 * KP + kk + tg]);
            af[1] = __float_as_uint(Ps[(row0 + 8) * KP + kk + tg]);
            af[2] = __float_as_uint(Ps[row0 * KP + kk + tg + 4]);
            af[3] = __float_as_uint(Ps[(row0 + 8) * KP + kk + tg + 4]);
#pragma unroll
            for (int nb = 0; nb < 8; nb++) {
                uint32_t bf[2];
                bf[0] = __float_as_uint(Vs[(kk + tg) * VP + nb * 8 + g]);
                bf[1] = __float_as_uint(Vs[(kk + tg + 4) * VP + nb * 8 + g]);
                mma_tf32(oacc[nb], af, bf);
            }
        }

        __syncthreads();
        if (t < qt) {
            PREFETCH_V(t + 1);
            if (t + 1 < qt) PREFETCH_K(t + 2, t & 1);
        }
    }
#undef PREFETCH_K
#undef PREFETCH_V

    const float inv0 = 1.f / l0, inv1 = 1.f / l1;
    const size_t gr0 = (size_t)(b * SEQ + qg0) * DM + h * HD;
    const size_t gr1 = (size_t)(b * SEQ + qg1) * DM + h * HD;
#pragma unroll
    for (int nb = 0; nb < 8; nb++) {
        const int col = nb * 8 + tg * 2;
        uint2 o0, o1;
        o0.x = f2tf32(oacc[nb][0] * inv0); o0.y = f2tf32(oacc[nb][1] * inv0);
        o1.x = f2tf32(oacc[nb][2] * inv1); o1.y = f2tf32(oacc[nb][3] * inv1);
        *reinterpret_cast<uint2*>(outp + gr0 + col) = o0;
        *reinterpret_cast<uint2*>(outp + gr1 + col) = o1;
    }
}

// ---------------------------------------------------------------------------
extern "C" void kernel_launch(void* const* d_in, const int* in_sizes, int n_in,
                              void* d_out, int out_size)
{
    const float* x      = (const float*)d_in[0];
    const float* qkv_w  = (const float*)d_in[1];
    const float* qkv_b  = (const float*)d_in[2];
    const float* out_w  = (const float*)d_in[3];
    const float* out_b  = (const float*)d_in[4];
    float* out = (float*)d_out;

    float *qkv_ptr, *attn_ptr, *xc_ptr, *w1_ptr, *w2_ptr;
    cudaGetSymbolAddress((void**)&qkv_ptr, g_qkv);
    cudaGetSymbolAddress((void**)&attn_ptr, g_attn);
    cudaGetSymbolAddress((void**)&xc_ptr, g_xc);
    cudaGetSymbolAddress((void**)&w1_ptr, g_w1);
    cudaGetSymbolAddress((void**)&w2_ptr, g_w2);

    const size_t gemm_smem = (size_t)(GSTAGES * (128 * GAP + 16 * GBP)) * 4;  // 75776
    cudaFuncSetAttribute(tf32_gemm_bias<0>, cudaFuncAttributeMaxDynamicSharedMemorySize,
                         (int)gemm_smem);
    cudaFuncSetAttribute(tf32_gemm_bias<1>, cudaFuncAttributeMaxDynamicSharedMemorySize,
                         (int)gemm_smem);
    const size_t swa_smem = (size_t)(64 * KP + 2 * 64 * KP + 64 * VP) * 4;    // 70656
    cudaFuncSetAttribute(swa_mma_kernel, cudaFuncAttributeMaxDynamicSharedMemorySize,
                         (int)swa_smem);

    // pre-round inputs/weights to tf32
    cvt_tf32_kernel<<<1024, 256>>>(x, xc_ptr, MTOT * DM / 4);
    cvt_tf32_kernel<<<1024, 256>>>(qkv_w, w1_ptr, DM * NQKV / 4);
    cvt_tf32_kernel<<<512, 256>>>(out_w, w2_ptr, DM * DM / 4);

    dim3 g1(NQKV / GBN, MTOT / GBM);
    tf32_gemm_bias<1><<<g1, 256, gemm_smem>>>(xc_ptr, w1_ptr, qkv_b, qkv_ptr, MTOT, NQKV, DM);

    dim3 ga(SEQ / 64, BATCH * NH);
    swa_mma_kernel<<<ga, 128, swa_smem>>>(qkv_ptr, attn_ptr);

    dim3 g2(DM / GBN, MTOT / GBM);
    tf32_gemm_bias<0><<<g2, 256, gemm_smem>>>(attn_ptr, w2_ptr, out_b, out, MTOT, DM, DM);
}

// round 9
// speedup vs baseline: 1.8341x; 1.8341x over previous
#include <cuda_runtime.h>
#include <cuda_fp16.h>
#include <math.h>
#include <stdint.h>

#define BATCH 2
#define SEQ 2048
#define NH 16
#define HD 64
#define DM 1024
#define WINDOW 512
#define MTOT (BATCH*SEQ)      // 4096
#define NQKV (3*DM)           // 3072

// fp16 GEMM tiling: CTA 128x128, 128 threads (4 warps 2x2, warp 64x64),
// GBK = 32 halves per stage, 3-stage cp.async ring.
#define GBK 32
#define HP 56        // smem pitch in halves (112B: 16B-aligned, conflict-free)
#define GSTAGES 3
#define GEMM_SMEM (GSTAGES * 2 * 128 * HP * 2)   // 86016 B

// attention smem pitch (halves): 72 (144B, 16B-aligned, conflict-free)
#define AP 72
#define ATT_SMEM ((64*AP + 2*64*AP + 64*AP) * 2) // 36864 B

__device__ __half g_x16[(size_t)MTOT * DM];
__device__ __half g_qkv16[(size_t)MTOT * NQKV];
__device__ __half g_vt16[(size_t)BATCH * NH * HD * SEQ];
__device__ __half g_attn16[(size_t)MTOT * DM];
__device__ __half g_w1t[(size_t)NQKV * DM];   // [N][K]
__device__ __half g_w2t[(size_t)DM * DM];     // [N][K]

__device__ __forceinline__ float ex2(float x) {
    float y;
    asm("ex2.approx.ftz.f32 %0, %1;" : "=f"(y) : "f"(x));
    return y;
}
// pack {lo, hi} floats -> f16x2 (first PTX source -> upper half)
__device__ __forceinline__ uint32_t pack_h2(float lo, float hi) {
    uint32_t u;
    asm("cvt.rn.f16x2.f32 %0, %1, %2;" : "=r"(u) : "f"(hi), "f"(lo));
    return u;
}
__device__ __forceinline__ void mma_f16(float c[4], const uint32_t a[4], const uint32_t b[2]) {
    asm volatile(
        "mma.sync.aligned.m16n8k16.row.col.f32.f16.f16.f32 "
        "{%0,%1,%2,%3}, {%4,%5,%6,%7}, {%8,%9}, {%0,%1,%2,%3};"
        : "+f"(c[0]), "+f"(c[1]), "+f"(c[2]), "+f"(c[3])
        : "r"(a[0]), "r"(a[1]), "r"(a[2]), "r"(a[3]), "r"(b[0]), "r"(b[1]));
}
__device__ __forceinline__ void cp_async16(void* dst, const void* src) {
    uint32_t s = (uint32_t)__cvta_generic_to_shared(dst);
    asm volatile("cp.async.ca.shared.global [%0], [%1], 16;" :: "r"(s), "l"(src));
}

// x: fp32 -> fp16 elementwise
__global__ __launch_bounds__(256) void cvt_h_kernel(const float* __restrict__ in,
                                                    __half* __restrict__ outp, int n4)
{
    int idx = blockIdx.x * 256 + threadIdx.x;
    int stride = gridDim.x * 256;
    for (; idx < n4; idx += stride) {
        float4 v = reinterpret_cast<const float4*>(in)[idx];
        uint2 u;
        u.x = pack_h2(v.x, v.y);
        u.y = pack_h2(v.z, v.w);
        reinterpret_cast<uint2*>(outp)[idx] = u;
    }
}

// W: fp32 [K][N] -> fp16 [N][K]
__global__ void trans_h_kernel(const float* __restrict__ in, __half* __restrict__ outp,
                               int Kd, int Nd)
{
    __shared__ float t[32][33];
    const int tx = threadIdx.x, ty = threadIdx.y;
    const int nb = blockIdx.x * 32;
    const int kb = blockIdx.y * 32;
#pragma unroll
    for (int j = 0; j < 32; j += 8)
        t[ty + j][tx] = in[(size_t)(kb + ty + j) * Nd + nb + tx];
    __syncthreads();
#pragma unroll
    for (int j = 0; j < 32; j += 8)
        outp[(size_t)(nb + ty + j) * Kd + kb + tx] = __float2half(t[tx][ty + j]);
}

// V slice of qkv16 -> per-head transposed [bh][hd][token]
__global__ __launch_bounds__(128) void vtrans_kernel(const __half* __restrict__ qkv,
                                                     __half* __restrict__ vt)
{
    __shared__ __half t[64][AP];
    const int tid = threadIdx.x;
    const int bh = blockIdx.y;
    const int b = bh >> 4, h = bh & 15;
    const int tb = blockIdx.x;
    const int r = tid >> 1;
    const int c0 = (tid & 1) * 32;

    const __half* src = qkv + (size_t)(b * SEQ + tb * 64 + r) * NQKV + 2 * DM + h * HD + c0;
#pragma unroll
    for (int c = 0; c < 32; c += 8)
        *reinterpret_cast<uint4*>(&t[r][c0 + c]) = *reinterpret_cast<const uint4*>(src + c);
    __syncthreads();
    __half* dst = vt + ((size_t)bh * HD + r) * SEQ + tb * 64 + c0;
#pragma unroll
    for (int c = 0; c < 32; c++) dst[c] = t[c0 + c][r];
}

// ---------------------------------------------------------------------------
// FP16 GEMM: C[M,N] = A[M,K] @ Bt[N,K]^T + bias. k16 MMA.
// OUTHALF=1 -> write fp16, else fp32.
// ---------------------------------------------------------------------------
template<int OUTHALF>
__global__ __launch_bounds__(128) void hgemm_bias(
    const __half* __restrict__ A, const __half* __restrict__ Bt,
    const float* __restrict__ bias, void* __restrict__ Cout,
    int M, int N, int K)
{
    extern __shared__ __half gh[];
    __half* As = gh;                          // [GSTAGES][128][HP]
    __half* Bs = gh + GSTAGES * 128 * HP;     // [GSTAGES][128][HP]

    const int tid  = threadIdx.x;
    const int lane = tid & 31;
    const int warp = tid >> 5;
    const int wm = warp & 1;
    const int wn = warp >> 1;
    const int g  = lane >> 2;
    const int tg = lane & 3;

    const int rowBase = blockIdx.y * 128;
    const int colBase = blockIdx.x * 128;
    const int nkt = K / GBK;

    float acc[4][8][4];
#pragma unroll
    for (int i = 0; i < 4; i++)
#pragma unroll
        for (int j = 0; j < 8; j++)
#pragma unroll
            for (int c = 0; c < 4; c++) acc[i][j][c] = 0.f;

    const int lrow = tid >> 2;
    const int lch  = (tid & 3) * 8;

#define ISSUE(KT, ST)                                                          \
    {                                                                          \
        __half* as_ = As + (ST) * (128 * HP);                                  \
        __half* bs_ = Bs + (ST) * (128 * HP);                                  \
        _Pragma("unroll")                                                      \
        for (int f = 0; f < 4; f++) {                                          \
            int row = lrow + f * 32;                                           \
            cp_async16(as_ + row * HP + lch,                                   \
                       A + (size_t)(rowBase + row) * K + (KT) * GBK + lch);    \
            cp_async16(bs_ + row * HP + lch,                                   \
                       Bt + (size_t)(colBase + row) * K + (KT) * GBK + lch);   \
        }                                                                      \
        asm volatile("cp.async.commit_group;");                                \
    }

    ISSUE(0, 0);
    ISSUE(1, 1);

    for (int kt = 0; kt < nkt; kt++) {
        if (kt + 1 < nkt) { asm volatile("cp.async.wait_group 1;"); }
        else              { asm volatile("cp.async.wait_group 0;"); }
        __syncthreads();

        const __half* as = As + (kt % 3) * (128 * HP);
        const __half* bs = Bs + (kt % 3) * (128 * HP);

#pragma unroll
        for (int ks = 0; ks < 2; ks++) {
            const int kk = ks * 16;
            uint32_t af[4][4];
#pragma unroll
            for (int mi = 0; mi < 4; mi++) {
                const int m = wm * 64 + mi * 16;
                af[mi][0] = *reinterpret_cast<const uint32_t*>(&as[(m + g) * HP + kk + tg * 2]);
                af[mi][1] = *reinterpret_cast<const uint32_t*>(&as[(m + g + 8) * HP + kk + tg * 2]);
                af[mi][2] = *reinterpret_cast<const uint32_t*>(&as[(m + g) * HP + kk + 8 + tg * 2]);
                af[mi][3] = *reinterpret_cast<const uint32_t*>(&as[(m + g + 8) * HP + kk + 8 + tg * 2]);
            }
            uint32_t bf[8][2];
#pragma unroll
            for (int nj = 0; nj < 8; nj++) {
                const int n = wn * 64 + nj * 8;
                bf[nj][0] = *reinterpret_cast<const uint32_t*>(&bs[(n + g) * HP + kk + tg * 2]);
                bf[nj][1] = *reinterpret_cast<const uint32_t*>(&bs[(n + g) * HP + kk + 8 + tg * 2]);
            }
#pragma unroll
            for (int mi = 0; mi < 4; mi++)
#pragma unroll
                for (int nj = 0; nj < 8; nj++)
                    mma_f16(acc[mi][nj], af[mi], bf[nj]);
        }

        if (kt + 2 < nkt) ISSUE(kt + 2, (kt + 2) % 3);
    }
#undef ISSUE

#pragma unroll
    for (int mi = 0; mi < 4; mi++) {
#pragma unroll
        for (int nj = 0; nj < 8; nj++) {
            const int col = colBase + wn * 64 + nj * 8 + tg * 2;
            const float bx = bias[col];
            const float by = bias[col + 1];
            const size_t r0 = (size_t)(rowBase + wm * 64 + mi * 16 + g);
            const size_t r1 = r0 + 8;
            float v00 = acc[mi][nj][0] + bx, v01 = acc[mi][nj][1] + by;
            float v10 = acc[mi][nj][2] + bx, v11 = acc[mi][nj][3] + by;
            if (OUTHALF) {
                __half* Ch = (__half*)Cout;
                *reinterpret_cast<uint32_t*>(Ch + r0 * N + col) = pack_h2(v00, v01);
                *reinterpret_cast<uint32_t*>(Ch + r1 * N + col) = pack_h2(v10, v11);
            } else {
                float* Cf = (float*)Cout;
                float2 o0 = {v00, v01}, o1 = {v10, v11};
                *reinterpret_cast<float2*>(Cf + r0 * N + col) = o0;
                *reinterpret_cast<float2*>(Cf + r1 * N + col) = o1;
            }
        }
    }
}

// ---------------------------------------------------------------------------
// Sliding-window attention, fp16 MMA (k16). P lives in registers.
// ---------------------------------------------------------------------------
__global__ __launch_bounds__(128, 3) void swa_h_kernel(const __half* __restrict__ qkv,
                                                       const __half* __restrict__ vt,
                                                       __half* __restrict__ outp)
{
    extern __shared__ __half hsm[];
    __half* Qs = hsm;                 // [64][AP]
    __half* Ks = Qs + 64 * AP;        // [2][64][AP]
    __half* Vs = Ks + 2 * 64 * AP;    // [64][AP]  (Vt tile: rows=hd, cols=keys)

    const int tid  = threadIdx.x;
    const int lane = tid & 31;
    const int warp = tid >> 5;
    const int g  = lane >> 2;
    const int tg = lane & 3;
    const int bh = blockIdx.y;
    const int b = bh >> 4;
    const int h = bh & 15;
    const int qt = blockIdx.x;
    const int q0 = qt * 64;

    const float QS = 0.125f * 1.4426950408889634f;   // 1/sqrt(64) * log2(e)

    const int r  = tid >> 1;
    const int c0 = (tid & 1) * 32;

#define PREFETCH_K(T, ST)                                                        \
    {                                                                            \
        const __half* ks = qkv + (size_t)(b * SEQ + (T) * 64 + r) * NQKV         \
                           + DM + h * HD + c0;                                   \
        __half* kd = Ks + (ST) * 64 * AP + r * AP + c0;                          \
        _Pragma("unroll")                                                        \
        for (int c = 0; c < 32; c += 8) cp_async16(kd + c, ks + c);              \
        asm volatile("cp.async.commit_group;");                                  \
    }
#define PREFETCH_V(T)                                                            \
    {                                                                            \
        const __half* vsrc = vt + ((size_t)bh * HD + r) * SEQ + (T) * 64 + c0;   \
        __half* vd = Vs + r * AP + c0;                                           \
        _Pragma("unroll")                                                        \
        for (int c = 0; c < 32; c += 8) cp_async16(vd + c, vsrc + c);            \
        asm volatile("cp.async.commit_group;");                                  \
    }

    int kstart = q0 - (WINDOW - 1);
    if (kstart < 0) kstart = 0;
    const int t0 = kstart >> 6;

    // group A: {Q, K(t0)}, group B: {V(t0)}, group C: {K(t0+1)} (only if t0<qt)
    {
        const __half* qsrc = qkv + (size_t)(b * SEQ + q0 + r) * NQKV + h * HD + c0;
        __half* qd = Qs + r * AP + c0;
#pragma unroll
        for (int c = 0; c < 32; c += 8) cp_async16(qd + c, qsrc + c);
        const __half* ks = qkv + (size_t)(b * SEQ + t0 * 64 + r) * NQKV + DM + h * HD + c0;
        __half* kd = Ks + (t0 & 1) * 64 * AP + r * AP + c0;
#pragma unroll
        for (int c = 0; c < 32; c += 8) cp_async16(kd + c, ks + c);
        asm volatile("cp.async.commit_group;");
    }
    PREFETCH_V(t0);
    if (t0 < qt) {
        PREFETCH_K(t0 + 1, (t0 + 1) & 1);
        asm volatile("cp.async.wait_group 2;");   // 3 groups pending -> A done
    } else {
        asm volatile("cp.async.wait_group 1;");   // 2 groups pending -> A done (R8 BUG FIX)
    }
    __syncthreads();   // Q (+K(t0)) visible to all threads

    // Q fragments in registers: 4 k16 steps
    const int row0 = warp * 16 + g;
    uint32_t qf[4][4];
#pragma unroll
    for (int ks = 0; ks < 4; ks++) {
        const int kk = ks * 16;
        qf[ks][0] = *reinterpret_cast<const uint32_t*>(&Qs[row0 * AP + kk + tg * 2]);
        qf[ks][1] = *reinterpret_cast<const uint32_t*>(&Qs[(row0 + 8) * AP + kk + tg * 2]);
        qf[ks][2] = *reinterpret_cast<const uint32_t*>(&Qs[row0 * AP + kk + 8 + tg * 2]);
        qf[ks][3] = *reinterpret_cast<const uint32_t*>(&Qs[(row0 + 8) * AP + kk + 8 + tg * 2]);
    }

    float oacc[8][4];
#pragma unroll
    for (int nb = 0; nb < 8; nb++)
#pragma unroll
        for (int c = 0; c < 4; c++) oacc[nb][c] = 0.f;
    float m0 = -INFINITY, m1 = -INFINITY, l0 = 0.f, l1 = 0.f;

    const int qg0 = q0 + row0;
    const int qg1 = qg0 + 8;

    for (int t = t0; t <= qt; t++) {
        if (t < qt) { asm volatile("cp.async.wait_group 2;"); }
        else        { asm volatile("cp.async.wait_group 1;"); }
        __syncthreads();   // K(t) visible

        const __half* ks_ = Ks + (t & 1) * 64 * AP;

        // S = Q @ K^T (raw scores; scale folded into exp)
        float sacc[8][4];
#pragma unroll
        for (int nb = 0; nb < 8; nb++)
#pragma unroll
            for (int c = 0; c < 4; c++) sacc[nb][c] = 0.f;

#pragma unroll
        for (int ks = 0; ks < 4; ks++) {
            const int kk = ks * 16;
#pragma unroll
            for (int nb = 0; nb < 8; nb++) {
                uint32_t bf[2];
                bf[0] = *reinterpret_cast<const uint32_t*>(&ks_[(nb * 8 + g) * AP + kk + tg * 2]);
                bf[1] = *reinterpret_cast<const uint32_t*>(&ks_[(nb * 8 + g) * AP + kk + 8 + tg * 2]);
                mma_f16(sacc[nb], qf[ks], bf);
            }
        }

        // boundary masking only
        const int delta = q0 - t * 64;
        if (delta == 0 || delta == WINDOW) {
#pragma unroll
            for (int nb = 0; nb < 8; nb++) {
                const int kg0 = t * 64 + nb * 8 + tg * 2;
                const int kg1 = kg0 + 1;
                int d;
                d = qg0 - kg0; if (d < 0 || d >= WINDOW) sacc[nb][0] = -INFINITY;
                d = qg0 - kg1; if (d < 0 || d >= WINDOW) sacc[nb][1] = -INFINITY;
                d = qg1 - kg0; if (d < 0 || d >= WINDOW) sacc[nb][2] = -INFINITY;
                d = qg1 - kg1; if (d < 0 || d >= WINDOW) sacc[nb][3] = -INFINITY;
            }
        }

        float mx0 = -INFINITY, mx1 = -INFINITY;
#pragma unroll
        for (int nb = 0; nb < 8; nb++) {
            mx0 = fmaxf(mx0, fmaxf(sacc[nb][0], sacc[nb][1]));
            mx1 = fmaxf(mx1, fmaxf(sacc[nb][2], sacc[nb][3]));
        }
        mx0 = fmaxf(mx0, __shfl_xor_sync(0xffffffffu, mx0, 1));
        mx0 = fmaxf(mx0, __shfl_xor_sync(0xffffffffu, mx0, 2));
        mx1 = fmaxf(mx1, __shfl_xor_sync(0xffffffffu, mx1, 1));
        mx1 = fmaxf(mx1, __shfl_xor_sync(0xffffffffu, mx1, 2));

        const float mn0 = fmaxf(m0, mx0), mn1 = fmaxf(m1, mx1);
        const float md0 = (mn0 == -INFINITY) ? 0.f : mn0;
        const float md1 = (mn1 == -INFINITY) ? 0.f : mn1;
        const float sc0 = ex2((m0 - md0) * QS);
        const float sc1 = ex2((m1 - md1) * QS);
        const float mdq0 = md0 * QS;
        const float mdq1 = md1 * QS;

        // P in registers as f16x2 A-fragments
        uint32_t ph[8][2];
        float ps0 = 0.f, ps1 = 0.f;
#pragma unroll
        for (int nb = 0; nb < 8; nb++) {
            float p00 = ex2(fmaf(sacc[nb][0], QS, -mdq0));
            float p01 = ex2(fmaf(sacc[nb][1], QS, -mdq0));
            float p10 = ex2(fmaf(sacc[nb][2], QS, -mdq1));
            float p11 = ex2(fmaf(sacc[nb][3], QS, -mdq1));
            ps0 += p00 + p01;
            ps1 += p10 + p11;
            ph[nb][0] = pack_h2(p00, p01);   // row g
            ph[nb][1] = pack_h2(p10, p11);   // row g+8
        }
        ps0 += __shfl_xor_sync(0xffffffffu, ps0, 1);
        ps0 += __shfl_xor_sync(0xffffffffu, ps0, 2);
        ps1 += __shfl_xor_sync(0xffffffffu, ps1, 1);
        ps1 += __shfl_xor_sync(0xffffffffu, ps1, 2);

        l0 = l0 * sc0 + ps0;
        l1 = l1 * sc1 + ps1;
        m0 = mn0; m1 = mn1;
#pragma unroll
        for (int nb = 0; nb < 8; nb++) {
            oacc[nb][0] *= sc0; oacc[nb][1] *= sc0;
            oacc[nb][2] *= sc1; oacc[nb][3] *= sc1;
        }

        if (t < qt) { asm volatile("cp.async.wait_group 1;"); }
        else        { asm volatile("cp.async.wait_group 0;"); }
        __syncthreads();   // V(t) visible to all threads (cross-thread copies)

        // O += P @ V  (A = P from registers, B = Vt tile [hd][key])
#pragma unroll
        for (int ks = 0; ks < 4; ks++) {
            const int kk = ks * 16;
            uint32_t af[4];
            af[0] = ph[2 * ks][0];
            af[1] = ph[2 * ks][1];
            af[2] = ph[2 * ks + 1][0];
            af[3] = ph[2 * ks + 1][1];
#pragma unroll
            for (int nb = 0; nb < 8; nb++) {
                uint32_t bf[2];
                bf[0] = *reinterpret_cast<const uint32_t*>(&Vs[(nb * 8 + g) * AP + kk + tg * 2]);
                bf[1] = *reinterpret_cast<const uint32_t*>(&Vs[(nb * 8 + g) * AP + kk + 8 + tg * 2]);
                mma_f16(oacc[nb], af, bf);
            }
        }

        __syncthreads();   // all warps finished with Vs & K stage buffers
        if (t < qt) {
            PREFETCH_V(t + 1);
            if (t + 1 < qt) PREFETCH_K(t + 2, t & 1);
        }
    }
#undef PREFETCH_K
#undef PREFETCH_V

    // epilogue: write fp16 (feeds GEMM2)
    const float inv0 = 1.f / l0, inv1 = 1.f / l1;
    const size_t gr0 = (size_t)(b * SEQ + qg0) * DM + h * HD;
    const size_t gr1 = (size_t)(b * SEQ + qg1) * DM + h * HD;
#pragma unroll
    for (int nb = 0; nb < 8; nb++) {
        const int col = nb * 8 + tg * 2;
        *reinterpret_cast<uint32_t*>(outp + gr0 + col) =
            pack_h2(oacc[nb][0] * inv0, oacc[nb][1] * inv0);
        *reinterpret_cast<uint32_t*>(outp + gr1 + col) =
            pack_h2(oacc[nb][2] * inv1, oacc[nb][3] * inv1);
    }
}

// ---------------------------------------------------------------------------
extern "C" void kernel_launch(void* const* d_in, const int* in_sizes, int n_in,
                              void* d_out, int out_size)
{
    const float* x      = (const float*)d_in[0];
    const float* qkv_w  = (const float*)d_in[1];
    const float* qkv_b  = (const float*)d_in[2];
    const float* out_w  = (const float*)d_in[3];
    const float* out_b  = (const float*)d_in[4];
    float* out = (float*)d_out;

    __half *x16, *qkv16, *vt16, *attn16, *w1t, *w2t;
    cudaGetSymbolAddress((void**)&x16, g_x16);
    cudaGetSymbolAddress((void**)&qkv16, g_qkv16);
    cudaGetSymbolAddress((void**)&vt16, g_vt16);
    cudaGetSymbolAddress((void**)&attn16, g_attn16);
    cudaGetSymbolAddress((void**)&w1t, g_w1t);
    cudaGetSymbolAddress((void**)&w2t, g_w2t);

    cudaFuncSetAttribute(hgemm_bias<0>, cudaFuncAttributeMaxDynamicSharedMemorySize, GEMM_SMEM);
    cudaFuncSetAttribute(hgemm_bias<1>, cudaFuncAttributeMaxDynamicSharedMemorySize, GEMM_SMEM);
    cudaFuncSetAttribute(swa_h_kernel, cudaFuncAttributeMaxDynamicSharedMemorySize, ATT_SMEM);

    // pre-passes: x -> fp16, weights -> fp16 transposed [N][K]
    cvt_h_kernel<<<1024, 256>>>(x, x16, MTOT * DM / 4);
    trans_h_kernel<<<dim3(NQKV / 32, DM / 32), dim3(32, 8)>>>(qkv_w, w1t, DM, NQKV);
    trans_h_kernel<<<dim3(DM / 32, DM / 32), dim3(32, 8)>>>(out_w, w2t, DM, DM);

    // 1) QKV projection (fp16 tensor cores) -> fp16 qkv
    dim3 g1(NQKV / 128, MTOT / 128);
    hgemm_bias<1><<<g1, 128, GEMM_SMEM>>>(x16, w1t, qkv_b, qkv16, MTOT, NQKV, DM);

    // 1b) transpose V per head for PV B-operand
    vtrans_kernel<<<dim3(SEQ / 64, BATCH * NH), 128>>>(qkv16, vt16);

    // 2) sliding-window attention (fp16 MMA, P in registers)
    dim3 ga(SEQ / 64, BATCH * NH);
    swa_h_kernel<<<ga, 128, ATT_SMEM>>>(qkv16, vt16, attn16);

    // 3) output projection (fp16 tensor cores) -> fp32 out
    dim3 g2(DM / 128, MTOT / 128);
    hgemm_bias<0><<<g2, 128, GEMM_SMEM>>>(attn16, w2t, out_b, out, MTOT, DM, DM);
}

// round 10
// speedup vs baseline: 2.1369x; 1.1651x over previous
#include <cuda_runtime.h>
#include <cuda_fp16.h>
#include <math.h>
#include <stdint.h>

#define BATCH 2
#define SEQ 2048
#define NH 16
#define HD 64
#define DM 1024
#define WINDOW 512
#define MTOT (BATCH*SEQ)      // 4096
#define NQKV (3*DM)           // 3072

// fp16 GEMM tiling: CTA 128x128, 128 threads (4 warps 2x2, warp 64x64),
// GBK = 32 halves per stage, 3-stage cp.async ring.
#define GBK 32
#define HP 56        // smem pitch in halves (112B = 16*7: ldmatrix conflict-free)
#define GSTAGES 3
#define GEMM_SMEM (GSTAGES * 2 * 128 * HP * 2)   // 86016 B

// attention smem pitch (halves): 72 (144B = 16*9: ldmatrix conflict-free)
#define AP 72
#define ATT_SMEM ((64*AP + 2*64*AP + 64*AP) * 2) // 36864 B

__device__ __half g_x16[(size_t)MTOT * DM];
__device__ __half g_qkv16[(size_t)MTOT * NQKV];
__device__ __half g_vt16[(size_t)BATCH * NH * HD * SEQ];
__device__ __half g_attn16[(size_t)MTOT * DM];
__device__ __half g_w1t[(size_t)NQKV * DM];   // [N][K]
__device__ __half g_w2t[(size_t)DM * DM];     // [N][K]

__device__ __forceinline__ float ex2(float x) {
    float y;
    asm("ex2.approx.ftz.f32 %0, %1;" : "=f"(y) : "f"(x));
    return y;
}
__device__ __forceinline__ uint32_t pack_h2(float lo, float hi) {
    uint32_t u;
    asm("cvt.rn.f16x2.f32 %0, %1, %2;" : "=r"(u) : "f"(hi), "f"(lo));
    return u;
}
__device__ __forceinline__ void mma_f16(float c[4], const uint32_t a[4], const uint32_t b[2]) {
    asm volatile(
        "mma.sync.aligned.m16n8k16.row.col.f32.f16.f16.f32 "
        "{%0,%1,%2,%3}, {%4,%5,%6,%7}, {%8,%9}, {%0,%1,%2,%3};"
        : "+f"(c[0]), "+f"(c[1]), "+f"(c[2]), "+f"(c[3])
        : "r"(a[0]), "r"(a[1]), "r"(a[2]), "r"(a[3]), "r"(b[0]), "r"(b[1]));
}
__device__ __forceinline__ void cp_async16(void* dst, const void* src) {
    uint32_t s = (uint32_t)__cvta_generic_to_shared(dst);
    asm volatile("cp.async.ca.shared.global [%0], [%1], 16;" :: "r"(s), "l"(src));
}
__device__ __forceinline__ uint32_t smem_u32(const void* p) {
    return (uint32_t)__cvta_generic_to_shared(p);
}
__device__ __forceinline__ void ldsm_x4(uint32_t& r0, uint32_t& r1, uint32_t& r2,
                                        uint32_t& r3, uint32_t addr) {
    asm volatile("ldmatrix.sync.aligned.m8n8.x4.shared.b16 {%0,%1,%2,%3}, [%4];"
                 : "=r"(r0), "=r"(r1), "=r"(r2), "=r"(r3) : "r"(addr));
}

// x: fp32 -> fp16 elementwise
__global__ __launch_bounds__(256) void cvt_h_kernel(const float* __restrict__ in,
                                                    __half* __restrict__ outp, int n4)
{
    int idx = blockIdx.x * 256 + threadIdx.x;
    int stride = gridDim.x * 256;
    for (; idx < n4; idx += stride) {
        float4 v = reinterpret_cast<const float4*>(in)[idx];
        uint2 u;
        u.x = pack_h2(v.x, v.y);
        u.y = pack_h2(v.z, v.w);
        reinterpret_cast<uint2*>(outp)[idx] = u;
    }
}

// W: fp32 [K][N] -> fp16 [N][K]
__global__ void trans_h_kernel(const float* __restrict__ in, __half* __restrict__ outp,
                               int Kd, int Nd)
{
    __shared__ float t[32][33];
    const int tx = threadIdx.x, ty = threadIdx.y;
    const int nb = blockIdx.x * 32;
    const int kb = blockIdx.y * 32;
#pragma unroll
    for (int j = 0; j < 32; j += 8)
        t[ty + j][tx] = in[(size_t)(kb + ty + j) * Nd + nb + tx];
    __syncthreads();
#pragma unroll
    for (int j = 0; j < 32; j += 8)
        outp[(size_t)(nb + ty + j) * Kd + kb + tx] = __float2half(t[tx][ty + j]);
}

// V slice of qkv16 -> per-head transposed [bh][hd][token]
__global__ __launch_bounds__(128) void vtrans_kernel(const __half* __restrict__ qkv,
                                                     __half* __restrict__ vt)
{
    __shared__ __half t[64][AP];
    const int tid = threadIdx.x;
    const int bh = blockIdx.y;
    const int b = bh >> 4, h = bh & 15;
    const int tb = blockIdx.x;
    const int r = tid >> 1;
    const int c0 = (tid & 1) * 32;

    const __half* src = qkv + (size_t)(b * SEQ + tb * 64 + r) * NQKV + 2 * DM + h * HD + c0;
#pragma unroll
    for (int c = 0; c < 32; c += 8)
        *reinterpret_cast<uint4*>(&t[r][c0 + c]) = *reinterpret_cast<const uint4*>(src + c);
    __syncthreads();
    __half* dst = vt + ((size_t)bh * HD + r) * SEQ + tb * 64 + c0;
#pragma unroll
    for (int c = 0; c < 32; c++) dst[c] = t[c0 + c][r];
}

// ---------------------------------------------------------------------------
// FP16 GEMM: C[M,N] = A[M,K] @ Bt[N,K]^T + bias. k16 MMA + ldmatrix.
// ---------------------------------------------------------------------------
template<int OUTHALF>
__global__ __launch_bounds__(128) void hgemm_bias(
    const __half* __restrict__ A, const __half* __restrict__ Bt,
    const float* __restrict__ bias, void* __restrict__ Cout,
    int M, int N, int K)
{
    extern __shared__ __half gh[];
    __half* As = gh;                          // [GSTAGES][128][HP]
    __half* Bs = gh + GSTAGES * 128 * HP;     // [GSTAGES][128][HP]

    const int tid  = threadIdx.x;
    const int lane = tid & 31;
    const int warp = tid >> 5;
    const int wm = warp & 1;
    const int wn = warp >> 1;
    const int g  = lane >> 2;
    const int tg = lane & 3;

    // ldmatrix per-lane geometry
    const int la  = (lane & 7) + ((lane >> 3) & 1) * 8;   // A: row-in-16
    const int lak = (lane >> 4) * 8;                      // A: k-half
    const int lb  = (lane & 7) + ((lane >> 4) << 3);      // B: row-in-16
    const int lbk = ((lane >> 3) & 1) * 8;                // B: k-half

    const int rowBase = blockIdx.y * 128;
    const int colBase = blockIdx.x * 128;
    const int nkt = K / GBK;

    float acc[4][8][4];
#pragma unroll
    for (int i = 0; i < 4; i++)
#pragma unroll
        for (int j = 0; j < 8; j++)
#pragma unroll
            for (int c = 0; c < 4; c++) acc[i][j][c] = 0.f;

    const int lrow = tid >> 2;
    const int lch  = (tid & 3) * 8;

#define ISSUE(KT, ST)                                                          \
    {                                                                          \
        __half* as_ = As + (ST) * (128 * HP);                                  \
        __half* bs_ = Bs + (ST) * (128 * HP);                                  \
        _Pragma("unroll")                                                      \
        for (int f = 0; f < 4; f++) {                                          \
            int row = lrow + f * 32;                                           \
            cp_async16(as_ + row * HP + lch,                                   \
                       A + (size_t)(rowBase + row) * K + (KT) * GBK + lch);    \
            cp_async16(bs_ + row * HP + lch,                                   \
                       Bt + (size_t)(colBase + row) * K + (KT) * GBK + lch);   \
        }                                                                      \
        asm volatile("cp.async.commit_group;");                                \
    }

    ISSUE(0, 0);
    ISSUE(1, 1);

    const uint32_t asb0 = smem_u32(As);
    const uint32_t bsb0 = smem_u32(Bs);

    for (int kt = 0; kt < nkt; kt++) {
        if (kt + 1 < nkt) { asm volatile("cp.async.wait_group 1;"); }
        else              { asm volatile("cp.async.wait_group 0;"); }
        __syncthreads();

        const uint32_t asb = asb0 + (kt % 3) * (128 * HP * 2);
        const uint32_t bsb = bsb0 + (kt % 3) * (128 * HP * 2);

#pragma unroll
        for (int ks = 0; ks < 2; ks++) {
            const int kk = ks * 16;
            uint32_t af[4][4];
#pragma unroll
            for (int mi = 0; mi < 4; mi++) {
                const int m = wm * 64 + mi * 16;
                ldsm_x4(af[mi][0], af[mi][1], af[mi][2], af[mi][3],
                        asb + 2 * ((m + la) * HP + kk + lak));
            }
            uint32_t bf[8][2];
#pragma unroll
            for (int p = 0; p < 4; p++) {
                const int n = wn * 64 + p * 16;
                ldsm_x4(bf[2 * p][0], bf[2 * p][1], bf[2 * p + 1][0], bf[2 * p + 1][1],
                        bsb + 2 * ((n + lb) * HP + kk + lbk));
            }
#pragma unroll
            for (int mi = 0; mi < 4; mi++)
#pragma unroll
                for (int nj = 0; nj < 8; nj++)
                    mma_f16(acc[mi][nj], af[mi], bf[nj]);
        }

        if (kt + 2 < nkt) ISSUE(kt + 2, (kt + 2) % 3);
    }
#undef ISSUE

#pragma unroll
    for (int mi = 0; mi < 4; mi++) {
#pragma unroll
        for (int nj = 0; nj < 8; nj++) {
            const int col = colBase + wn * 64 + nj * 8 + tg * 2;
            const float bx = bias[col];
            const float by = bias[col + 1];
            const size_t r0 = (size_t)(rowBase + wm * 64 + mi * 16 + g);
            const size_t r1 = r0 + 8;
            float v00 = acc[mi][nj][0] + bx, v01 = acc[mi][nj][1] + by;
            float v10 = acc[mi][nj][2] + bx, v11 = acc[mi][nj][3] + by;
            if (OUTHALF) {
                __half* Ch = (__half*)Cout;
                *reinterpret_cast<uint32_t*>(Ch + r0 * N + col) = pack_h2(v00, v01);
                *reinterpret_cast<uint32_t*>(Ch + r1 * N + col) = pack_h2(v10, v11);
            } else {
                float* Cf = (float*)Cout;
                float2 o0 = {v00, v01}, o1 = {v10, v11};
                *reinterpret_cast<float2*>(Cf + r0 * N + col) = o0;
                *reinterpret_cast<float2*>(Cf + r1 * N + col) = o1;
            }
        }
    }
}

// ---------------------------------------------------------------------------
// Sliding-window attention, fp16 MMA + ldmatrix. P lives in registers.
// ---------------------------------------------------------------------------
__global__ __launch_bounds__(128, 3) void swa_h_kernel(const __half* __restrict__ qkv,
                                                       const __half* __restrict__ vt,
                                                       __half* __restrict__ outp)
{
    extern __shared__ __half hsm[];
    __half* Qs = hsm;                 // [64][AP]
    __half* Ks = Qs + 64 * AP;        // [2][64][AP]
    __half* Vs = Ks + 2 * 64 * AP;    // [64][AP]  (Vt tile: rows=hd, cols=keys)

    const int tid  = threadIdx.x;
    const int lane = tid & 31;
    const int warp = tid >> 5;
    const int g  = lane >> 2;
    const int tg = lane & 3;
    const int bh = blockIdx.y;
    const int b = bh >> 4;
    const int h = bh & 15;
    const int qt = blockIdx.x;
    const int q0 = qt * 64;

    const float QS = 0.125f * 1.4426950408889634f;   // 1/sqrt(64) * log2(e)

    const int la  = (lane & 7) + ((lane >> 3) & 1) * 8;
    const int lak = (lane >> 4) * 8;
    const int lb  = (lane & 7) + ((lane >> 4) << 3);
    const int lbk = ((lane >> 3) & 1) * 8;

    const int r  = tid >> 1;
    const int c0 = (tid & 1) * 32;

#define PREFETCH_K(T, ST)                                                        \
    {                                                                            \
        const __half* ks = qkv + (size_t)(b * SEQ + (T) * 64 + r) * NQKV         \
                           + DM + h * HD + c0;                                   \
        __half* kd = Ks + (ST) * 64 * AP + r * AP + c0;                          \
        _Pragma("unroll")                                                        \
        for (int c = 0; c < 32; c += 8) cp_async16(kd + c, ks + c);              \
        asm volatile("cp.async.commit_group;");                                  \
    }
#define PREFETCH_V(T)                                                            \
    {                                                                            \
        const __half* vsrc = vt + ((size_t)bh * HD + r) * SEQ + (T) * 64 + c0;   \
        __half* vd = Vs + r * AP + c0;                                           \
        _Pragma("unroll")                                                        \
        for (int c = 0; c < 32; c += 8) cp_async16(vd + c, vsrc + c);            \
        asm volatile("cp.async.commit_group;");                                  \
    }

    int kstart = q0 - (WINDOW - 1);
    if (kstart < 0) kstart = 0;
    const int t0 = kstart >> 6;

    // group A: {Q, K(t0)}, group B: {V(t0)}, group C: {K(t0+1)} (only if t0<qt)
    {
        const __half* qsrc = qkv + (size_t)(b * SEQ + q0 + r) * NQKV + h * HD + c0;
        __half* qd = Qs + r * AP + c0;
#pragma unroll
        for (int c = 0; c < 32; c += 8) cp_async16(qd + c, qsrc + c);
        const __half* ks = qkv + (size_t)(b * SEQ + t0 * 64 + r) * NQKV + DM + h * HD + c0;
        __half* kd = Ks + (t0 & 1) * 64 * AP + r * AP + c0;
#pragma unroll
        for (int c = 0; c < 32; c += 8) cp_async16(kd + c, ks + c);
        asm volatile("cp.async.commit_group;");
    }
    PREFETCH_V(t0);
    if (t0 < qt) {
        PREFETCH_K(t0 + 1, (t0 + 1) & 1);
        asm volatile("cp.async.wait_group 2;");
    } else {
        asm volatile("cp.async.wait_group 1;");
    }
    __syncthreads();   // Q (+K(t0)) visible

    // Q fragments via ldmatrix: 4 k16 steps
    const int row0 = warp * 16 + g;
    const uint32_t qsb = smem_u32(Qs);
    const uint32_t ksb0 = smem_u32(Ks);
    const uint32_t vsb = smem_u32(Vs);
    uint32_t qf[4][4];
#pragma unroll
    for (int ks = 0; ks < 4; ks++) {
        ldsm_x4(qf[ks][0], qf[ks][1], qf[ks][2], qf[ks][3],
                qsb + 2 * ((warp * 16 + la) * AP + ks * 16 + lak));
    }

    float oacc[8][4];
#pragma unroll
    for (int nb = 0; nb < 8; nb++)
#pragma unroll
        for (int c = 0; c < 4; c++) oacc[nb][c] = 0.f;
    float m0 = -INFINITY, m1 = -INFINITY, l0 = 0.f, l1 = 0.f;

    const int qg0 = q0 + row0;
    const int qg1 = qg0 + 8;

    for (int t = t0; t <= qt; t++) {
        if (t < qt) { asm volatile("cp.async.wait_group 2;"); }
        else        { asm volatile("cp.async.wait_group 1;"); }
        __syncthreads();   // K(t) visible

        const uint32_t ksb = ksb0 + (t & 1) * (64 * AP * 2);

        float sacc[8][4];
#pragma unroll
        for (int nb = 0; nb < 8; nb++)
#pragma unroll
            for (int c = 0; c < 4; c++) sacc[nb][c] = 0.f;

#pragma unroll
        for (int ks = 0; ks < 4; ks++) {
            const int kk = ks * 16;
            uint32_t bf[8][2];
#pragma unroll
            for (int p = 0; p < 4; p++) {
                ldsm_x4(bf[2 * p][0], bf[2 * p][1], bf[2 * p + 1][0], bf[2 * p + 1][1],
                        ksb + 2 * ((p * 16 + lb) * AP + kk + lbk));
            }
#pragma unroll
            for (int nb = 0; nb < 8; nb++)
                mma_f16(sacc[nb], qf[ks], bf[nb]);
        }

        // boundary masking only
        const int delta = q0 - t * 64;
        if (delta == 0 || delta == WINDOW) {
#pragma unroll
            for (int nb = 0; nb < 8; nb++) {
                const int kg0 = t * 64 + nb * 8 + tg * 2;
                const int kg1 = kg0 + 1;
                int d;
                d = qg0 - kg0; if (d < 0 || d >= WINDOW) sacc[nb][0] = -INFINITY;
                d = qg0 - kg1; if (d < 0 || d >= WINDOW) sacc[nb][1] = -INFINITY;
                d = qg1 - kg0; if (d < 0 || d >= WINDOW) sacc[nb][2] = -INFINITY;
                d = qg1 - kg1; if (d < 0 || d >= WINDOW) sacc[nb][3] = -INFINITY;
            }
        }

        float mx0 = -INFINITY, mx1 = -INFINITY;
#pragma unroll
        for (int nb = 0; nb < 8; nb++) {
            mx0 = fmaxf(mx0, fmaxf(sacc[nb][0], sacc[nb][1]));
            mx1 = fmaxf(mx1, fmaxf(sacc[nb][2], sacc[nb][3]));
        }
        mx0 = fmaxf(mx0, __shfl_xor_sync(0xffffffffu, mx0, 1));
        mx0 = fmaxf(mx0, __shfl_xor_sync(0xffffffffu, mx0, 2));
        mx1 = fmaxf(mx1, __shfl_xor_sync(0xffffffffu, mx1, 1));
        mx1 = fmaxf(mx1, __shfl_xor_sync(0xffffffffu, mx1, 2));

        const float mn0 = fmaxf(m0, mx0), mn1 = fmaxf(m1, mx1);
        const float md0 = (mn0 == -INFINITY) ? 0.f : mn0;
        const float md1 = (mn1 == -INFINITY) ? 0.f : mn1;
        const float sc0 = ex2((m0 - md0) * QS);
        const float sc1 = ex2((m1 - md1) * QS);
        const float mdq0 = md0 * QS;
        const float mdq1 = md1 * QS;

        uint32_t ph[8][2];
        float ps0 = 0.f, ps1 = 0.f;
#pragma unroll
        for (int nb = 0; nb < 8; nb++) {
            float p00 = ex2(fmaf(sacc[nb][0], QS, -mdq0));
            float p01 = ex2(fmaf(sacc[nb][1], QS, -mdq0));
            float p10 = ex2(fmaf(sacc[nb][2], QS, -mdq1));
            float p11 = ex2(fmaf(sacc[nb][3], QS, -mdq1));
            ps0 += p00 + p01;
            ps1 += p10 + p11;
            ph[nb][0] = pack_h2(p00, p01);
            ph[nb][1] = pack_h2(p10, p11);
        }
        ps0 += __shfl_xor_sync(0xffffffffu, ps0, 1);
        ps0 += __shfl_xor_sync(0xffffffffu, ps0, 2);
        ps1 += __shfl_xor_sync(0xffffffffu, ps1, 1);
        ps1 += __shfl_xor_sync(0xffffffffu, ps1, 2);

        l0 = l0 * sc0 + ps0;
        l1 = l1 * sc1 + ps1;
        m0 = mn0; m1 = mn1;
#pragma unroll
        for (int nb = 0; nb < 8; nb++) {
            oacc[nb][0] *= sc0; oacc[nb][1] *= sc0;
            oacc[nb][2] *= sc1; oacc[nb][3] *= sc1;
        }

        if (t < qt) { asm volatile("cp.async.wait_group 1;"); }
        else        { asm volatile("cp.async.wait_group 0;"); }
        __syncthreads();   // V(t) visible

        // O += P @ V
#pragma unroll
        for (int ks = 0; ks < 4; ks++) {
            const int kk = ks * 16;
            uint32_t af[4];
            af[0] = ph[2 * ks][0];
            af[1] = ph[2 * ks][1];
            af[2] = ph[2 * ks + 1][0];
            af[3] = ph[2 * ks + 1][1];
            uint32_t bf[8][2];
#pragma unroll
            for (int p = 0; p < 4; p++) {
                ldsm_x4(bf[2 * p][0], bf[2 * p][1], bf[2 * p + 1][0], bf[2 * p + 1][1],
                        vsb + 2 * ((p * 16 + lb) * AP + kk + lbk));
            }
#pragma unroll
            for (int nb = 0; nb < 8; nb++)
                mma_f16(oacc[nb], af, bf[nb]);
        }

        __syncthreads();
        if (t < qt) {
            PREFETCH_V(t + 1);
            if (t + 1 < qt) PREFETCH_K(t + 2, t & 1);
        }
    }
#undef PREFETCH_K
#undef PREFETCH_V

    const float inv0 = 1.f / l0, inv1 = 1.f / l1;
    const size_t gr0 = (size_t)(b * SEQ + qg0) * DM + h * HD;
    const size_t gr1 = (size_t)(b * SEQ + qg1) * DM + h * HD;
#pragma unroll
    for (int nb = 0; nb < 8; nb++) {
        const int col = nb * 8 + tg * 2;
        *reinterpret_cast<uint32_t*>(outp + gr0 + col) =
            pack_h2(oacc[nb][0] * inv0, oacc[nb][1] * inv0);
        *reinterpret_cast<uint32_t*>(outp + gr1 + col) =
            pack_h2(oacc[nb][2] * inv1, oacc[nb][3] * inv1);
    }
}

// ---------------------------------------------------------------------------
extern "C" void kernel_launch(void* const* d_in, const int* in_sizes, int n_in,
                              void* d_out, int out_size)
{
    const float* x      = (const float*)d_in[0];
    const float* qkv_w  = (const float*)d_in[1];
    const float* qkv_b  = (const float*)d_in[2];
    const float* out_w  = (const float*)d_in[3];
    const float* out_b  = (const float*)d_in[4];
    float* out = (float*)d_out;

    __half *x16, *qkv16, *vt16, *attn16, *w1t, *w2t;
    cudaGetSymbolAddress((void**)&x16, g_x16);
    cudaGetSymbolAddress((void**)&qkv16, g_qkv16);
    cudaGetSymbolAddress((void**)&vt16, g_vt16);
    cudaGetSymbolAddress((void**)&attn16, g_attn16);
    cudaGetSymbolAddress((void**)&w1t, g_w1t);
    cudaGetSymbolAddress((void**)&w2t, g_w2t);

    cudaFuncSetAttribute(hgemm_bias<0>, cudaFuncAttributeMaxDynamicSharedMemorySize, GEMM_SMEM);
    cudaFuncSetAttribute(hgemm_bias<1>, cudaFuncAttributeMaxDynamicSharedMemorySize, GEMM_SMEM);
    cudaFuncSetAttribute(swa_h_kernel, cudaFuncAttributeMaxDynamicSharedMemorySize, ATT_SMEM);

    cvt_h_kernel<<<1024, 256>>>(x, x16, MTOT * DM / 4);
    trans_h_kernel<<<dim3(NQKV / 32, DM / 32), dim3(32, 8)>>>(qkv_w, w1t, DM, NQKV);
    trans_h_kernel<<<dim3(DM / 32, DM / 32), dim3(32, 8)>>>(out_w, w2t, DM, DM);

    dim3 g1(NQKV / 128, MTOT / 128);
    hgemm_bias<1><<<g1, 128, GEMM_SMEM>>>(x16, w1t, qkv_b, qkv16, MTOT, NQKV, DM);

    vtrans_kernel<<<dim3(SEQ / 64, BATCH * NH), 128>>>(qkv16, vt16);

    dim3 ga(SEQ / 64, BATCH * NH);
    swa_h_kernel<<<ga, 128, ATT_SMEM>>>(qkv16, vt16, attn16);

    dim3 g2(DM / 128, MTOT / 128);
    hgemm_bias<0><<<g2, 128, GEMM_SMEM>>>(attn16, w2t, out_b, out, MTOT, DM, DM);
}

// round 11
// speedup vs baseline: 2.4602x; 1.1513x over previous
#include <cuda_runtime.h>
#include <cuda_fp16.h>
#include <math.h>
#include <stdint.h>

#define BATCH 2
#define SEQ 2048
#define NH 16
#define HD 64
#define DM 1024
#define WINDOW 512
#define MTOT (BATCH*SEQ)      // 4096
#define NQKV (3*DM)           // 3072

// fp16 GEMM tiling: CTA 128x128, 128 threads (4 warps 2x2, warp 64x64),
// GBK = 32 halves per stage, 3-stage cp.async ring.
#define GBK 32
#define HP 56        // smem pitch in halves (112B = 16*7: ldmatrix conflict-free)
#define GSTAGES 3
#define GEMM_SMEM (GSTAGES * 2 * 128 * HP * 2)   // 86016 B

// attention: BQ=128 query tile, 64-wide key tiles, pitch 72 halves (144B)
#define AP 72
#define ATT_SMEM ((128*AP + 2*64*AP + 64*AP) * 2) // 46080 B

__device__ __half g_x16[(size_t)MTOT * DM];
__device__ __half g_qkv16[(size_t)MTOT * NQKV];
__device__ __half g_attn16[(size_t)MTOT * DM];
__device__ __half g_w1t[(size_t)NQKV * DM];   // [N][K]
__device__ __half g_w2t[(size_t)DM * DM];     // [N][K]

__device__ __forceinline__ float ex2(float x) {
    float y;
    asm("ex2.approx.ftz.f32 %0, %1;" : "=f"(y) : "f"(x));
    return y;
}
__device__ __forceinline__ uint32_t pack_h2(float lo, float hi) {
    uint32_t u;
    asm("cvt.rn.f16x2.f32 %0, %1, %2;" : "=r"(u) : "f"(hi), "f"(lo));
    return u;
}
__device__ __forceinline__ void mma_f16(float c[4], const uint32_t a[4], const uint32_t b[2]) {
    asm volatile(
        "mma.sync.aligned.m16n8k16.row.col.f32.f16.f16.f32 "
        "{%0,%1,%2,%3}, {%4,%5,%6,%7}, {%8,%9}, {%0,%1,%2,%3};"
        : "+f"(c[0]), "+f"(c[1]), "+f"(c[2]), "+f"(c[3])
        : "r"(a[0]), "r"(a[1]), "r"(a[2]), "r"(a[3]), "r"(b[0]), "r"(b[1]));
}
__device__ __forceinline__ void cp_async16(void* dst, const void* src) {
    uint32_t s = (uint32_t)__cvta_generic_to_shared(dst);
    asm volatile("cp.async.ca.shared.global [%0], [%1], 16;" :: "r"(s), "l"(src));
}
__device__ __forceinline__ uint32_t smem_u32(const void* p) {
    return (uint32_t)__cvta_generic_to_shared(p);
}
__device__ __forceinline__ void ldsm_x4(uint32_t& r0, uint32_t& r1, uint32_t& r2,
                                        uint32_t& r3, uint32_t addr) {
    asm volatile("ldmatrix.sync.aligned.m8n8.x4.shared.b16 {%0,%1,%2,%3}, [%4];"
                 : "=r"(r0), "=r"(r1), "=r"(r2), "=r"(r3) : "r"(addr));
}
__device__ __forceinline__ void ldsm_x4_trans(uint32_t& r0, uint32_t& r1, uint32_t& r2,
                                              uint32_t& r3, uint32_t addr) {
    asm volatile("ldmatrix.sync.aligned.m8n8.x4.trans.shared.b16 {%0,%1,%2,%3}, [%4];"
                 : "=r"(r0), "=r"(r1), "=r"(r2), "=r"(r3) : "r"(addr));
}

// x: fp32 -> fp16 elementwise
__global__ __launch_bounds__(256) void cvt_h_kernel(const float* __restrict__ in,
                                                    __half* __restrict__ outp, int n4)
{
    int idx = blockIdx.x * 256 + threadIdx.x;
    int stride = gridDim.x * 256;
    for (; idx < n4; idx += stride) {
        float4 v = reinterpret_cast<const float4*>(in)[idx];
        uint2 u;
        u.x = pack_h2(v.x, v.y);
        u.y = pack_h2(v.z, v.w);
        reinterpret_cast<uint2*>(outp)[idx] = u;
    }
}

// W: fp32 [K][N] -> fp16 [N][K]
__global__ void trans_h_kernel(const float* __restrict__ in, __half* __restrict__ outp,
                               int Kd, int Nd)
{
    __shared__ float t[32][33];
    const int tx = threadIdx.x, ty = threadIdx.y;
    const int nb = blockIdx.x * 32;
    const int kb = blockIdx.y * 32;
#pragma unroll
    for (int j = 0; j < 32; j += 8)
        t[ty + j][tx] = in[(size_t)(kb + ty + j) * Nd + nb + tx];
    __syncthreads();
#pragma unroll
    for (int j = 0; j < 32; j += 8)
        outp[(size_t)(nb + ty + j) * Kd + kb + tx] = __float2half(t[tx][ty + j]);
}

// ---------------------------------------------------------------------------
// FP16 GEMM: C[M,N] = A[M,K] @ Bt[N,K]^T + bias. k16 MMA + ldmatrix.
// (unchanged from round 10 — measured at ~98% of legacy HMMA roofline)
// ---------------------------------------------------------------------------
template<int OUTHALF>
__global__ __launch_bounds__(128) void hgemm_bias(
    const __half* __restrict__ A, const __half* __restrict__ Bt,
    const float* __restrict__ bias, void* __restrict__ Cout,
    int M, int N, int K)
{
    extern __shared__ __half gh[];
    __half* As = gh;
    __half* Bs = gh + GSTAGES * 128 * HP;

    const int tid  = threadIdx.x;
    const int lane = tid & 31;
    const int warp = tid >> 5;
    const int wm = warp & 1;
    const int wn = warp >> 1;
    const int g  = lane >> 2;
    const int tg = lane & 3;

    const int la  = (lane & 7) + ((lane >> 3) & 1) * 8;
    const int lak = (lane >> 4) * 8;
    const int lb  = (lane & 7) + ((lane >> 4) << 3);
    const int lbk = ((lane >> 3) & 1) * 8;

    const int rowBase = blockIdx.y * 128;
    const int colBase = blockIdx.x * 128;
    const int nkt = K / GBK;

    float acc[4][8][4];
#pragma unroll
    for (int i = 0; i < 4; i++)
#pragma unroll
        for (int j = 0; j < 8; j++)
#pragma unroll
            for (int c = 0; c < 4; c++) acc[i][j][c] = 0.f;

    const int lrow = tid >> 2;
    const int lch  = (tid & 3) * 8;

#define ISSUE(KT, ST)                                                          \
    {                                                                          \
        __half* as_ = As + (ST) * (128 * HP);                                  \
        __half* bs_ = Bs + (ST) * (128 * HP);                                  \
        _Pragma("unroll")                                                      \
        for (int f = 0; f < 4; f++) {                                          \
            int row = lrow + f * 32;                                           \
            cp_async16(as_ + row * HP + lch,                                   \
                       A + (size_t)(rowBase + row) * K + (KT) * GBK + lch);    \
            cp_async16(bs_ + row * HP + lch,                                   \
                       Bt + (size_t)(colBase + row) * K + (KT) * GBK + lch);   \
        }                                                                      \
        asm volatile("cp.async.commit_group;");                                \
    }

    ISSUE(0, 0);
    ISSUE(1, 1);

    const uint32_t asb0 = smem_u32(As);
    const uint32_t bsb0 = smem_u32(Bs);

    for (int kt = 0; kt < nkt; kt++) {
        if (kt + 1 < nkt) { asm volatile("cp.async.wait_group 1;"); }
        else              { asm volatile("cp.async.wait_group 0;"); }
        __syncthreads();

        const uint32_t asb = asb0 + (kt % 3) * (128 * HP * 2);
        const uint32_t bsb = bsb0 + (kt % 3) * (128 * HP * 2);

#pragma unroll
        for (int ks = 0; ks < 2; ks++) {
            const int kk = ks * 16;
            uint32_t af[4][4];
#pragma unroll
            for (int mi = 0; mi < 4; mi++) {
                const int m = wm * 64 + mi * 16;
                ldsm_x4(af[mi][0], af[mi][1], af[mi][2], af[mi][3],
                        asb + 2 * ((m + la) * HP + kk + lak));
            }
            uint32_t bf[8][2];
#pragma unroll
            for (int p = 0; p < 4; p++) {
                const int n = wn * 64 + p * 16;
                ldsm_x4(bf[2 * p][0], bf[2 * p][1], bf[2 * p + 1][0], bf[2 * p + 1][1],
                        bsb + 2 * ((n + lb) * HP + kk + lbk));
            }
#pragma unroll
            for (int mi = 0; mi < 4; mi++)
#pragma unroll
                for (int nj = 0; nj < 8; nj++)
                    mma_f16(acc[mi][nj], af[mi], bf[nj]);
        }

        if (kt + 2 < nkt) ISSUE(kt + 2, (kt + 2) % 3);
    }
#undef ISSUE

#pragma unroll
    for (int mi = 0; mi < 4; mi++) {
#pragma unroll
        for (int nj = 0; nj < 8; nj++) {
            const int col = colBase + wn * 64 + nj * 8 + tg * 2;
            const float bx = bias[col];
            const float by = bias[col + 1];
            const size_t r0 = (size_t)(rowBase + wm * 64 + mi * 16 + g);
            const size_t r1 = r0 + 8;
            float v00 = acc[mi][nj][0] + bx, v01 = acc[mi][nj][1] + by;
            float v10 = acc[mi][nj][2] + bx, v11 = acc[mi][nj][3] + by;
            if (OUTHALF) {
                __half* Ch = (__half*)Cout;
                *reinterpret_cast<uint32_t*>(Ch + r0 * N + col) = pack_h2(v00, v01);
                *reinterpret_cast<uint32_t*>(Ch + r1 * N + col) = pack_h2(v10, v11);
            } else {
                float* Cf = (float*)Cout;
                float2 o0 = {v00, v01}, o1 = {v10, v11};
                *reinterpret_cast<float2*>(Cf + r0 * N + col) = o0;
                *reinterpret_cast<float2*>(Cf + r1 * N + col) = o1;
            }
        }
    }
}

// ---------------------------------------------------------------------------
// Sliding-window attention v2: BQ=128 (256 threads, 8 warps), 64-wide K tiles.
// V loaded straight from qkv; PV B-fragments via ldmatrix.trans.
// Per 128 query rows: 10 key tiles instead of 18 (0.56x MMA+softmax work).
// ---------------------------------------------------------------------------
__global__ __launch_bounds__(256) void swa_h_kernel(const __half* __restrict__ qkv,
                                                    __half* __restrict__ outp)
{
    extern __shared__ __half hsm[];
    __half* Qs = hsm;                  // [128][AP]
    __half* Ks = Qs + 128 * AP;        // [2][64][AP]
    __half* Vs = Ks + 2 * 64 * AP;     // [64][AP]  (row layout: [token][hd])

    const int tid  = threadIdx.x;
    const int lane = tid & 31;
    const int warp = tid >> 5;         // 0..7
    const int g  = lane >> 2;
    const int tg = lane & 3;
    const int bh = blockIdx.y;
    const int b = bh >> 4;
    const int h = bh & 15;
    const int qt = blockIdx.x;
    const int q0 = qt * 128;

    const float QS = 0.125f * 1.4426950408889634f;   // 1/sqrt(64) * log2(e)

    const int la  = (lane & 7) + ((lane >> 3) & 1) * 8;
    const int lak = (lane >> 4) * 8;
    const int lb  = (lane & 7) + ((lane >> 4) << 3);
    const int lbk = ((lane >> 3) & 1) * 8;

    // loader geometry (256 threads)
    const int qr = tid >> 1;           // Q rows 0..127
    const int qc = (tid & 1) * 32;
    const int kr = tid >> 2;           // K/V rows 0..63
    const int kc = (tid & 3) * 8;

#define PREFETCH_K(T, ST)                                                        \
    {                                                                            \
        const __half* ks = qkv + (size_t)(b * SEQ + (T) * 64 + kr) * NQKV        \
                           + DM + h * HD + kc;                                   \
        __half* kd = Ks + (ST) * 64 * AP + kr * AP + kc;                         \
        cp_async16(kd, ks);                                                      \
        cp_async16(kd + 32, ks + 32);                                            \
        asm volatile("cp.async.commit_group;");                                  \
    }
#define PREFETCH_V(T)                                                            \
    {                                                                            \
        const __half* vs = qkv + (size_t)(b * SEQ + (T) * 64 + kr) * NQKV        \
                           + 2 * DM + h * HD + kc;                               \
        __half* vd = Vs + kr * AP + kc;                                          \
        cp_async16(vd, vs);                                                      \
        cp_async16(vd + 32, vs + 32);                                            \
        asm volatile("cp.async.commit_group;");                                  \
    }

    int kstart = q0 - (WINDOW - 1);
    if (kstart < 0) kstart = 0;
    const int t0 = kstart >> 6;
    const int t1 = 2 * qt + 1;         // last key tile (covers rows up to q0+127)

    // prologue: group A {Q, K(t0)}, group B {V(t0)}, group C {K(t0+1)}  (t0 < t1 always)
    {
        const __half* qsrc = qkv + (size_t)(b * SEQ + q0 + qr) * NQKV + h * HD + qc;
        __half* qd = Qs + qr * AP + qc;
        cp_async16(qd, qsrc);
        cp_async16(qd + 8, qsrc + 8);
        cp_async16(qd + 16, qsrc + 16);
        cp_async16(qd + 24, qsrc + 24);
        const __half* ks = qkv + (size_t)(b * SEQ + t0 * 64 + kr) * NQKV + DM + h * HD + kc;
        __half* kd = Ks + (t0 & 1) * 64 * AP + kr * AP + kc;
        cp_async16(kd, ks);
        cp_async16(kd + 32, ks + 32);
        asm volatile("cp.async.commit_group;");
    }
    PREFETCH_V(t0);
    PREFETCH_K(t0 + 1, (t0 + 1) & 1);
    asm volatile("cp.async.wait_group 2;");
    __syncthreads();   // Q (+K(t0)) visible

    const int row0 = warp * 16 + g;
    const uint32_t qsb = smem_u32(Qs);
    const uint32_t ksb0 = smem_u32(Ks);
    const uint32_t vsb = smem_u32(Vs);
    uint32_t qf[4][4];
#pragma unroll
    for (int ks = 0; ks < 4; ks++) {
        ldsm_x4(qf[ks][0], qf[ks][1], qf[ks][2], qf[ks][3],
                qsb + 2 * ((warp * 16 + la) * AP + ks * 16 + lak));
    }

    float oacc[8][4];
#pragma unroll
    for (int nb = 0; nb < 8; nb++)
#pragma unroll
        for (int c = 0; c < 4; c++) oacc[nb][c] = 0.f;
    float m0 = -INFINITY, m1 = -INFINITY, l0 = 0.f, l1 = 0.f;

    const int qg0 = q0 + row0;
    const int qg1 = qg0 + 8;

    for (int t = t0; t <= t1; t++) {
        if (t < t1) { asm volatile("cp.async.wait_group 2;"); }
        else        { asm volatile("cp.async.wait_group 1;"); }
        __syncthreads();   // K(t) visible

        const uint32_t ksb = ksb0 + (t & 1) * (64 * AP * 2);

        float sacc[8][4];
#pragma unroll
        for (int nb = 0; nb < 8; nb++)
#pragma unroll
            for (int c = 0; c < 4; c++) sacc[nb][c] = 0.f;

#pragma unroll
        for (int ks = 0; ks < 4; ks++) {
            const int kk = ks * 16;
            uint32_t bf[8][2];
#pragma unroll
            for (int p = 0; p < 4; p++) {
                ldsm_x4(bf[2 * p][0], bf[2 * p][1], bf[2 * p + 1][0], bf[2 * p + 1][1],
                        ksb + 2 * ((p * 16 + lb) * AP + kk + lbk));
            }
#pragma unroll
            for (int nb = 0; nb < 8; nb++)
                mma_f16(sacc[nb], qf[ks], bf[nb]);
        }

        // masking: diagonal tiles (delta <= 0) and window-edge tiles (delta >= W-64)
        const int delta = q0 - t * 64;
        if (delta <= 0 || delta >= WINDOW - 64) {
#pragma unroll
            for (int nb = 0; nb < 8; nb++) {
                const int kg0 = t * 64 + nb * 8 + tg * 2;
                const int kg1 = kg0 + 1;
                int d;
                d = qg0 - kg0; if (d < 0 || d >= WINDOW) sacc[nb][0] = -INFINITY;
                d = qg0 - kg1; if (d < 0 || d >= WINDOW) sacc[nb][1] = -INFINITY;
                d = qg1 - kg0; if (d < 0 || d >= WINDOW) sacc[nb][2] = -INFINITY;
                d = qg1 - kg1; if (d < 0 || d >= WINDOW) sacc[nb][3] = -INFINITY;
            }
        }

        float mx0 = -INFINITY, mx1 = -INFINITY;
#pragma unroll
        for (int nb = 0; nb < 8; nb++) {
            mx0 = fmaxf(mx0, fmaxf(sacc[nb][0], sacc[nb][1]));
            mx1 = fmaxf(mx1, fmaxf(sacc[nb][2], sacc[nb][3]));
        }
        mx0 = fmaxf(mx0, __shfl_xor_sync(0xffffffffu, mx0, 1));
        mx0 = fmaxf(mx0, __shfl_xor_sync(0xffffffffu, mx0, 2));
        mx1 = fmaxf(mx1, __shfl_xor_sync(0xffffffffu, mx1, 1));
        mx1 = fmaxf(mx1, __shfl_xor_sync(0xffffffffu, mx1, 2));

        const float mn0 = fmaxf(m0, mx0), mn1 = fmaxf(m1, mx1);
        const float md0 = (mn0 == -INFINITY) ? 0.f : mn0;
        const float md1 = (mn1 == -INFINITY) ? 0.f : mn1;
        const float sc0 = ex2((m0 - md0) * QS);
        const float sc1 = ex2((m1 - md1) * QS);
        const float mdq0 = md0 * QS;
        const float mdq1 = md1 * QS;

        uint32_t ph[8][2];
        float ps0 = 0.f, ps1 = 0.f;
#pragma unroll
        for (int nb = 0; nb < 8; nb++) {
            float p00 = ex2(fmaf(sacc[nb][0], QS, -mdq0));
            float p01 = ex2(fmaf(sacc[nb][1], QS, -mdq0));
            float p10 = ex2(fmaf(sacc[nb][2], QS, -mdq1));
            float p11 = ex2(fmaf(sacc[nb][3], QS, -mdq1));
            ps0 += p00 + p01;
            ps1 += p10 + p11;
            ph[nb][0] = pack_h2(p00, p01);
            ph[nb][1] = pack_h2(p10, p11);
        }
        ps0 += __shfl_xor_sync(0xffffffffu, ps0, 1);
        ps0 += __shfl_xor_sync(0xffffffffu, ps0, 2);
        ps1 += __shfl_xor_sync(0xffffffffu, ps1, 1);
        ps1 += __shfl_xor_sync(0xffffffffu, ps1, 2);

        l0 = l0 * sc0 + ps0;
        l1 = l1 * sc1 + ps1;
        m0 = mn0; m1 = mn1;
#pragma unroll
        for (int nb = 0; nb < 8; nb++) {
            oacc[nb][0] *= sc0; oacc[nb][1] *= sc0;
            oacc[nb][2] *= sc1; oacc[nb][3] *= sc1;
        }

        if (t < t1) { asm volatile("cp.async.wait_group 1;"); }
        else        { asm volatile("cp.async.wait_group 0;"); }
        __syncthreads();   // V(t) visible

        // O += P @ V   (B-frags from row-major V via ldmatrix.trans)
#pragma unroll
        for (int ks = 0; ks < 4; ks++) {
            const int kk = ks * 16;
            uint32_t af[4];
            af[0] = ph[2 * ks][0];
            af[1] = ph[2 * ks][1];
            af[2] = ph[2 * ks + 1][0];
            af[3] = ph[2 * ks + 1][1];
            uint32_t bf[8][2];
#pragma unroll
            for (int p = 0; p < 4; p++) {
                ldsm_x4_trans(bf[2 * p][0], bf[2 * p][1], bf[2 * p + 1][0], bf[2 * p + 1][1],
                              vsb + 2 * ((kk + la) * AP + p * 16 + lak));
            }
#pragma unroll
            for (int nb = 0; nb < 8; nb++)
                mma_f16(oacc[nb], af, bf[nb]);
        }

        __syncthreads();   // all warps done with Vs & K stage buffers
        if (t < t1) {
            PREFETCH_V(t + 1);
            if (t + 1 < t1) PREFETCH_K(t + 2, t & 1);
        }
    }
#undef PREFETCH_K
#undef PREFETCH_V

    // epilogue: write fp16 (feeds GEMM2)
    const float inv0 = 1.f / l0, inv1 = 1.f / l1;
    const size_t gr0 = (size_t)(b * SEQ + qg0) * DM + h * HD;
    const size_t gr1 = (size_t)(b * SEQ + qg1) * DM + h * HD;
#pragma unroll
    for (int nb = 0; nb < 8; nb++) {
        const int col = nb * 8 + tg * 2;
        *reinterpret_cast<uint32_t*>(outp + gr0 + col) =
            pack_h2(oacc[nb][0] * inv0, oacc[nb][1] * inv0);
        *reinterpret_cast<uint32_t*>(outp + gr1 + col) =
            pack_h2(oacc[nb][2] * inv1, oacc[nb][3] * inv1);
    }
}

// ---------------------------------------------------------------------------
extern "C" void kernel_launch(void* const* d_in, const int* in_sizes, int n_in,
                              void* d_out, int out_size)
{
    const float* x      = (const float*)d_in[0];
    const float* qkv_w  = (const float*)d_in[1];
    const float* qkv_b  = (const float*)d_in[2];
    const float* out_w  = (const float*)d_in[3];
    const float* out_b  = (const float*)d_in[4];
    float* out = (float*)d_out;

    __half *x16, *qkv16, *attn16, *w1t, *w2t;
    cudaGetSymbolAddress((void**)&x16, g_x16);
    cudaGetSymbolAddress((void**)&qkv16, g_qkv16);
    cudaGetSymbolAddress((void**)&attn16, g_attn16);
    cudaGetSymbolAddress((void**)&w1t, g_w1t);
    cudaGetSymbolAddress((void**)&w2t, g_w2t);

    cudaFuncSetAttribute(hgemm_bias<0>, cudaFuncAttributeMaxDynamicSharedMemorySize, GEMM_SMEM);
    cudaFuncSetAttribute(hgemm_bias<1>, cudaFuncAttributeMaxDynamicSharedMemorySize, GEMM_SMEM);
    cudaFuncSetAttribute(swa_h_kernel, cudaFuncAttributeMaxDynamicSharedMemorySize, ATT_SMEM);

    cvt_h_kernel<<<1024, 256>>>(x, x16, MTOT * DM / 4);
    trans_h_kernel<<<dim3(NQKV / 32, DM / 32), dim3(32, 8)>>>(qkv_w, w1t, DM, NQKV);
    trans_h_kernel<<<dim3(DM / 32, DM / 32), dim3(32, 8)>>>(out_w, w2t, DM, DM);

    dim3 g1(NQKV / 128, MTOT / 128);
    hgemm_bias<1><<<g1, 128, GEMM_SMEM>>>(x16, w1t, qkv_b, qkv16, MTOT, NQKV, DM);

    dim3 ga(SEQ / 128, BATCH * NH);
    swa_h_kernel<<<ga, 256, ATT_SMEM>>>(qkv16, attn16);

    dim3 g2(DM / 128, MTOT / 128);
    hgemm_bias<0><<<g2, 128, GEMM_SMEM>>>(attn16, w2t, out_b, out, MTOT, DM, DM);
}

// round 12
// speedup vs baseline: 2.5509x; 1.0369x over previous
#include <cuda_runtime.h>
#include <cuda_fp16.h>
#include <math.h>
#include <stdint.h>

#define BATCH 2
#define SEQ 2048
#define NH 16
#define HD 64
#define DM 1024
#define WINDOW 512
#define MTOT (BATCH*SEQ)      // 4096
#define NQKV (3*DM)           // 3072

// fp16 GEMM tiling: CTA 128x128, 128 threads (4 warps 2x2, warp 64x64),
// GBK = 32 halves per stage, 3-stage cp.async ring.
#define GBK 32
#define HP 56        // smem pitch in halves (112B = 16*7: ldmatrix conflict-free)
#define GSTAGES 3
#define GEMM_SMEM (GSTAGES * 2 * 128 * HP * 2)   // 86016 B

// attention: BQ=128 query tile, 64-wide key tiles, pitch 72 halves (144B)
#define AP 72
#define ATT_SMEM ((128*AP + 2*64*AP + 64*AP) * 2) // 46080 B

// fused pre-pass grid layout
#define PRE_W1_BLOCKS (NQKV / 32 * (DM / 32))    // 3072
#define PRE_W2_BLOCKS (DM / 32 * (DM / 32))      // 1024
#define PRE_CVT_BLOCKS 512
#define PRE_BLOCKS (PRE_W1_BLOCKS + PRE_W2_BLOCKS + PRE_CVT_BLOCKS)

__device__ __half g_x16[(size_t)MTOT * DM];
__device__ __half g_qkv16[(size_t)MTOT * NQKV];
__device__ __half g_attn16[(size_t)MTOT * DM];
__device__ __half g_w1t[(size_t)NQKV * DM];   // [N][K]
__device__ __half g_w2t[(size_t)DM * DM];     // [N][K]

__device__ __forceinline__ float ex2(float x) {
    float y;
    asm("ex2.approx.ftz.f32 %0, %1;" : "=f"(y) : "f"(x));
    return y;
}
__device__ __forceinline__ uint32_t pack_h2(float lo, float hi) {
    uint32_t u;
    asm("cvt.rn.f16x2.f32 %0, %1, %2;" : "=r"(u) : "f"(hi), "f"(lo));
    return u;
}
__device__ __forceinline__ void mma_f16(float c[4], const uint32_t a[4], const uint32_t b[2]) {
    asm volatile(
        "mma.sync.aligned.m16n8k16.row.col.f32.f16.f16.f32 "
        "{%0,%1,%2,%3}, {%4,%5,%6,%7}, {%8,%9}, {%0,%1,%2,%3};"
        : "+f"(c[0]), "+f"(c[1]), "+f"(c[2]), "+f"(c[3])
        : "r"(a[0]), "r"(a[1]), "r"(a[2]), "r"(a[3]), "r"(b[0]), "r"(b[1]));
}
__device__ __forceinline__ void cp_async16(void* dst, const void* src) {
    uint32_t s = (uint32_t)__cvta_generic_to_shared(dst);
    asm volatile("cp.async.ca.shared.global [%0], [%1], 16;" :: "r"(s), "l"(src));
}
__device__ __forceinline__ uint32_t smem_u32(const void* p) {
    return (uint32_t)__cvta_generic_to_shared(p);
}
__device__ __forceinline__ void ldsm_x4(uint32_t& r0, uint32_t& r1, uint32_t& r2,
                                        uint32_t& r3, uint32_t addr) {
    asm volatile("ldmatrix.sync.aligned.m8n8.x4.shared.b16 {%0,%1,%2,%3}, [%4];"
                 : "=r"(r0), "=r"(r1), "=r"(r2), "=r"(r3) : "r"(addr));
}
__device__ __forceinline__ void ldsm_x4_trans(uint32_t& r0, uint32_t& r1, uint32_t& r2,
                                              uint32_t& r3, uint32_t addr) {
    asm volatile("ldmatrix.sync.aligned.m8n8.x4.trans.shared.b16 {%0,%1,%2,%3}, [%4];"
                 : "=r"(r0), "=r"(r1), "=r"(r2), "=r"(r3) : "r"(addr));
}

// ---------------------------------------------------------------------------
// Fused pre-pass: one launch does (a) w1 transpose+cvt, (b) w2 transpose+cvt,
// (c) x fp32->fp16. All phases use 256-thread blocks.
// ---------------------------------------------------------------------------
__device__ __forceinline__ void trans_tile(const float* __restrict__ in,
                                           __half* __restrict__ outp,
                                           int Kd, int Nd, int nb, int kb, int tid)
{
    __shared__ float t[32][33];
    const int tx = tid & 31, ty = tid >> 5;   // 32 x 8
#pragma unroll
    for (int j = 0; j < 32; j += 8)
        t[ty + j][tx] = in[(size_t)(kb + ty + j) * Nd + nb + tx];
    __syncthreads();
#pragma unroll
    for (int j = 0; j < 32; j += 8)
        outp[(size_t)(nb + ty + j) * Kd + kb + tx] = __float2half(t[tx][ty + j]);
}

__global__ __launch_bounds__(256) void prepass_kernel(
    const float* __restrict__ x, const float* __restrict__ w1,
    const float* __restrict__ w2,
    __half* __restrict__ x16, __half* __restrict__ w1t, __half* __restrict__ w2t)
{
    const int bid = blockIdx.x;
    const int tid = threadIdx.x;

    if (bid < PRE_W1_BLOCKS) {
        const int nb = (bid % (NQKV / 32)) * 32;
        const int kb = (bid / (NQKV / 32)) * 32;
        trans_tile(w1, w1t, DM, NQKV, nb, kb, tid);
    } else if (bid < PRE_W1_BLOCKS + PRE_W2_BLOCKS) {
        const int b2 = bid - PRE_W1_BLOCKS;
        const int nb = (b2 % (DM / 32)) * 32;
        const int kb = (b2 / (DM / 32)) * 32;
        trans_tile(w2, w2t, DM, DM, nb, kb, tid);
    } else {
        const int b3 = bid - PRE_W1_BLOCKS - PRE_W2_BLOCKS;
        const int n4 = MTOT * DM / 4;
        int idx = b3 * 256 + tid;
        const int stride = PRE_CVT_BLOCKS * 256;
        for (; idx < n4; idx += stride) {
            float4 v = reinterpret_cast<const float4*>(x)[idx];
            uint2 u;
            u.x = pack_h2(v.x, v.y);
            u.y = pack_h2(v.z, v.w);
            reinterpret_cast<uint2*>(x16)[idx] = u;
        }
    }
}

// ---------------------------------------------------------------------------
// FP16 GEMM: C[M,N] = A[M,K] @ Bt[N,K]^T + bias. k16 MMA + ldmatrix.
// (unchanged — measured at ~98% of the legacy HMMA roofline)
// ---------------------------------------------------------------------------
template<int OUTHALF>
__global__ __launch_bounds__(128) void hgemm_bias(
    const __half* __restrict__ A, const __half* __restrict__ Bt,
    const float* __restrict__ bias, void* __restrict__ Cout,
    int M, int N, int K)
{
    extern __shared__ __half gh[];
    __half* As = gh;
    __half* Bs = gh + GSTAGES * 128 * HP;

    const int tid  = threadIdx.x;
    const int lane = tid & 31;
    const int warp = tid >> 5;
    const int wm = warp & 1;
    const int wn = warp >> 1;
    const int g  = lane >> 2;
    const int tg = lane & 3;

    const int la  = (lane & 7) + ((lane >> 3) & 1) * 8;
    const int lak = (lane >> 4) * 8;
    const int lb  = (lane & 7) + ((lane >> 4) << 3);
    const int lbk = ((lane >> 3) & 1) * 8;

    const int rowBase = blockIdx.y * 128;
    const int colBase = blockIdx.x * 128;
    const int nkt = K / GBK;

    float acc[4][8][4];
#pragma unroll
    for (int i = 0; i < 4; i++)
#pragma unroll
        for (int j = 0; j < 8; j++)
#pragma unroll
            for (int c = 0; c < 4; c++) acc[i][j][c] = 0.f;

    const int lrow = tid >> 2;
    const int lch  = (tid & 3) * 8;

#define ISSUE(KT, ST)                                                          \
    {                                                                          \
        __half* as_ = As + (ST) * (128 * HP);                                  \
        __half* bs_ = Bs + (ST) * (128 * HP);                                  \
        _Pragma("unroll")                                                      \
        for (int f = 0; f < 4; f++) {                                          \
            int row = lrow + f * 32;                                           \
            cp_async16(as_ + row * HP + lch,                                   \
                       A + (size_t)(rowBase + row) * K + (KT) * GBK + lch);    \
            cp_async16(bs_ + row * HP + lch,                                   \
                       Bt + (size_t)(colBase + row) * K + (KT) * GBK + lch);   \
        }                                                                      \
        asm volatile("cp.async.commit_group;");                                \
    }

    ISSUE(0, 0);
    ISSUE(1, 1);

    const uint32_t asb0 = smem_u32(As);
    const uint32_t bsb0 = smem_u32(Bs);

    for (int kt = 0; kt < nkt; kt++) {
        if (kt + 1 < nkt) { asm volatile("cp.async.wait_group 1;"); }
        else              { asm volatile("cp.async.wait_group 0;"); }
        __syncthreads();

        const uint32_t asb = asb0 + (kt % 3) * (128 * HP * 2);
        const uint32_t bsb = bsb0 + (kt % 3) * (128 * HP * 2);

#pragma unroll
        for (int ks = 0; ks < 2; ks++) {
            const int kk = ks * 16;
            uint32_t af[4][4];
#pragma unroll
            for (int mi = 0; mi < 4; mi++) {
                const int m = wm * 64 + mi * 16;
                ldsm_x4(af[mi][0], af[mi][1], af[mi][2], af[mi][3],
                        asb + 2 * ((m + la) * HP + kk + lak));
            }
            uint32_t bf[8][2];
#pragma unroll
            for (int p = 0; p < 4; p++) {
                const int n = wn * 64 + p * 16;
                ldsm_x4(bf[2 * p][0], bf[2 * p][1], bf[2 * p + 1][0], bf[2 * p + 1][1],
                        bsb + 2 * ((n + lb) * HP + kk + lbk));
            }
#pragma unroll
            for (int mi = 0; mi < 4; mi++)
#pragma unroll
                for (int nj = 0; nj < 8; nj++)
                    mma_f16(acc[mi][nj], af[mi], bf[nj]);
        }

        if (kt + 2 < nkt) ISSUE(kt + 2, (kt + 2) % 3);
    }
#undef ISSUE

#pragma unroll
    for (int mi = 0; mi < 4; mi++) {
#pragma unroll
        for (int nj = 0; nj < 8; nj++) {
            const int col = colBase + wn * 64 + nj * 8 + tg * 2;
            const float bx = bias[col];
            const float by = bias[col + 1];
            const size_t r0 = (size_t)(rowBase + wm * 64 + mi * 16 + g);
            const size_t r1 = r0 + 8;
            float v00 = acc[mi][nj][0] + bx, v01 = acc[mi][nj][1] + by;
            float v10 = acc[mi][nj][2] + bx, v11 = acc[mi][nj][3] + by;
            if (OUTHALF) {
                __half* Ch = (__half*)Cout;
                *reinterpret_cast<uint32_t*>(Ch + r0 * N + col) = pack_h2(v00, v01);
                *reinterpret_cast<uint32_t*>(Ch + r1 * N + col) = pack_h2(v10, v11);
            } else {
                float* Cf = (float*)Cout;
                float2 o0 = {v00, v01}, o1 = {v10, v11};
                *reinterpret_cast<float2*>(Cf + r0 * N + col) = o0;
                *reinterpret_cast<float2*>(Cf + r1 * N + col) = o1;
            }
        }
    }
}

// ---------------------------------------------------------------------------
// Sliding-window attention: BQ=128 (256 threads, 8 warps), 64-wide K tiles.
// (unchanged from round 11)
// ---------------------------------------------------------------------------
__global__ __launch_bounds__(256) void swa_h_kernel(const __half* __restrict__ qkv,
                                                    __half* __restrict__ outp)
{
    extern __shared__ __half hsm[];
    __half* Qs = hsm;                  // [128][AP]
    __half* Ks = Qs + 128 * AP;        // [2][64][AP]
    __half* Vs = Ks + 2 * 64 * AP;     // [64][AP]

    const int tid  = threadIdx.x;
    const int lane = tid & 31;
    const int warp = tid >> 5;
    const int g  = lane >> 2;
    const int tg = lane & 3;
    const int bh = blockIdx.y;
    const int b = bh >> 4;
    const int h = bh & 15;
    const int qt = blockIdx.x;
    const int q0 = qt * 128;

    const float QS = 0.125f * 1.4426950408889634f;

    const int la  = (lane & 7) + ((lane >> 3) & 1) * 8;
    const int lak = (lane >> 4) * 8;
    const int lb  = (lane & 7) + ((lane >> 4) << 3);
    const int lbk = ((lane >> 3) & 1) * 8;

    const int qr = tid >> 1;
    const int qc = (tid & 1) * 32;
    const int kr = tid >> 2;
    const int kc = (tid & 3) * 8;

#define PREFETCH_K(T, ST)                                                        \
    {                                                                            \
        const __half* ks = qkv + (size_t)(b * SEQ + (T) * 64 + kr) * NQKV        \
                           + DM + h * HD + kc;                                   \
        __half* kd = Ks + (ST) * 64 * AP + kr * AP + kc;                         \
        cp_async16(kd, ks);                                                      \
        cp_async16(kd + 32, ks + 32);                                            \
        asm volatile("cp.async.commit_group;");                                  \
    }
#define PREFETCH_V(T)                                                            \
    {                                                                            \
        const __half* vs = qkv + (size_t)(b * SEQ + (T) * 64 + kr) * NQKV        \
                           + 2 * DM + h * HD + kc;                               \
        __half* vd = Vs + kr * AP + kc;                                          \
        cp_async16(vd, vs);                                                      \
        cp_async16(vd + 32, vs + 32);                                            \
        asm volatile("cp.async.commit_group;");                                  \
    }

    int kstart = q0 - (WINDOW - 1);
    if (kstart < 0) kstart = 0;
    const int t0 = kstart >> 6;
    const int t1 = 2 * qt + 1;

    {
        const __half* qsrc = qkv + (size_t)(b * SEQ + q0 + qr) * NQKV + h * HD + qc;
        __half* qd = Qs + qr * AP + qc;
        cp_async16(qd, qsrc);
        cp_async16(qd + 8, qsrc + 8);
        cp_async16(qd + 16, qsrc + 16);
        cp_async16(qd + 24, qsrc + 24);
        const __half* ks = qkv + (size_t)(b * SEQ + t0 * 64 + kr) * NQKV + DM + h * HD + kc;
        __half* kd = Ks + (t0 & 1) * 64 * AP + kr * AP + kc;
        cp_async16(kd, ks);
        cp_async16(kd + 32, ks + 32);
        asm volatile("cp.async.commit_group;");
    }
    PREFETCH_V(t0);
    PREFETCH_K(t0 + 1, (t0 + 1) & 1);
    asm volatile("cp.async.wait_group 2;");
    __syncthreads();

    const int row0 = warp * 16 + g;
    const uint32_t qsb = smem_u32(Qs);
    const uint32_t ksb0 = smem_u32(Ks);
    const uint32_t vsb = smem_u32(Vs);
    uint32_t qf[4][4];
#pragma unroll
    for (int ks = 0; ks < 4; ks++) {
        ldsm_x4(qf[ks][0], qf[ks][1], qf[ks][2], qf[ks][3],
                qsb + 2 * ((warp * 16 + la) * AP + ks * 16 + lak));
    }

    float oacc[8][4];
#pragma unroll
    for (int nb = 0; nb < 8; nb++)
#pragma unroll
        for (int c = 0; c < 4; c++) oacc[nb][c] = 0.f;
    float m0 = -INFINITY, m1 = -INFINITY, l0 = 0.f, l1 = 0.f;

    const int qg0 = q0 + row0;
    const int qg1 = qg0 + 8;

    for (int t = t0; t <= t1; t++) {
        if (t < t1) { asm volatile("cp.async.wait_group 2;"); }
        else        { asm volatile("cp.async.wait_group 1;"); }
        __syncthreads();

        const uint32_t ksb = ksb0 + (t & 1) * (64 * AP * 2);

        float sacc[8][4];
#pragma unroll
        for (int nb = 0; nb < 8; nb++)
#pragma unroll
            for (int c = 0; c < 4; c++) sacc[nb][c] = 0.f;

#pragma unroll
        for (int ks = 0; ks < 4; ks++) {
            const int kk = ks * 16;
            uint32_t bf[8][2];
#pragma unroll
            for (int p = 0; p < 4; p++) {
                ldsm_x4(bf[2 * p][0], bf[2 * p][1], bf[2 * p + 1][0], bf[2 * p + 1][1],
                        ksb + 2 * ((p * 16 + lb) * AP + kk + lbk));
            }
#pragma unroll
            for (int nb = 0; nb < 8; nb++)
                mma_f16(sacc[nb], qf[ks], bf[nb]);
        }

        const int delta = q0 - t * 64;
        if (delta <= 0 || delta >= WINDOW - 64) {
#pragma unroll
            for (int nb = 0; nb < 8; nb++) {
                const int kg0 = t * 64 + nb * 8 + tg * 2;
                const int kg1 = kg0 + 1;
                int d;
                d = qg0 - kg0; if (d < 0 || d >= WINDOW) sacc[nb][0] = -INFINITY;
                d = qg0 - kg1; if (d < 0 || d >= WINDOW) sacc[nb][1] = -INFINITY;
                d = qg1 - kg0; if (d < 0 || d >= WINDOW) sacc[nb][2] = -INFINITY;
                d = qg1 - kg1; if (d < 0 || d >= WINDOW) sacc[nb][3] = -INFINITY;
            }
        }

        float mx0 = -INFINITY, mx1 = -INFINITY;
#pragma unroll
        for (int nb = 0; nb < 8; nb++) {
            mx0 = fmaxf(mx0, fmaxf(sacc[nb][0], sacc[nb][1]));
            mx1 = fmaxf(mx1, fmaxf(sacc[nb][2], sacc[nb][3]));
        }
        mx0 = fmaxf(mx0, __shfl_xor_sync(0xffffffffu, mx0, 1));
        mx0 = fmaxf(mx0, __shfl_xor_sync(0xffffffffu, mx0, 2));
        mx1 = fmaxf(mx1, __shfl_xor_sync(0xffffffffu, mx1, 1));
        mx1 = fmaxf(mx1, __shfl_xor_sync(0xffffffffu, mx1, 2));

        const float mn0 = fmaxf(m0, mx0), mn1 = fmaxf(m1, mx1);
        const float md0 = (mn0 == -INFINITY) ? 0.f : mn0;
        const float md1 = (mn1 == -INFINITY) ? 0.f : mn1;
        const float sc0 = ex2((m0 - md0) * QS);
        const float sc1 = ex2((m1 - md1) * QS);
        const float mdq0 = md0 * QS;
        const float mdq1 = md1 * QS;

        uint32_t ph[8][2];
        float ps0 = 0.f, ps1 = 0.f;
#pragma unroll
        for (int nb = 0; nb < 8; nb++) {
            float p00 = ex2(fmaf(sacc[nb][0], QS, -mdq0));
            float p01 = ex2(fmaf(sacc[nb][1], QS, -mdq0));
            float p10 = ex2(fmaf(sacc[nb][2], QS, -mdq1));
            float p11 = ex2(fmaf(sacc[nb][3], QS, -mdq1));
            ps0 += p00 + p01;
            ps1 += p10 + p11;
            ph[nb][0] = pack_h2(p00, p01);
            ph[nb][1] = pack_h2(p10, p11);
        }
        ps0 += __shfl_xor_sync(0xffffffffu, ps0, 1);
        ps0 += __shfl_xor_sync(0xffffffffu, ps0, 2);
        ps1 += __shfl_xor_sync(0xffffffffu, ps1, 1);
        ps1 += __shfl_xor_sync(0xffffffffu, ps1, 2);

        l0 = l0 * sc0 + ps0;
        l1 = l1 * sc1 + ps1;
        m0 = mn0; m1 = mn1;
#pragma unroll
        for (int nb = 0; nb < 8; nb++) {
            oacc[nb][0] *= sc0; oacc[nb][1] *= sc0;
            oacc[nb][2] *= sc1; oacc[nb][3] *= sc1;
        }

        if (t < t1) { asm volatile("cp.async.wait_group 1;"); }
        else        { asm volatile("cp.async.wait_group 0;"); }
        __syncthreads();

#pragma unroll
        for (int ks = 0; ks < 4; ks++) {
            const int kk = ks * 16;
            uint32_t af[4];
            af[0] = ph[2 * ks][0];
            af[1] = ph[2 * ks][1];
            af[2] = ph[2 * ks + 1][0];
            af[3] = ph[2 * ks + 1][1];
            uint32_t bf[8][2];
#pragma unroll
            for (int p = 0; p < 4; p++) {
                ldsm_x4_trans(bf[2 * p][0], bf[2 * p][1], bf[2 * p + 1][0], bf[2 * p + 1][1],
                              vsb + 2 * ((kk + la) * AP + p * 16 + lak));
            }
#pragma unroll
            for (int nb = 0; nb < 8; nb++)
                mma_f16(oacc[nb], af, bf[nb]);
        }

        __syncthreads();
        if (t < t1) {
            PREFETCH_V(t + 1);
            if (t + 1 < t1) PREFETCH_K(t + 2, t & 1);
        }
    }
#undef PREFETCH_K
#undef PREFETCH_V

    const float inv0 = 1.f / l0, inv1 = 1.f / l1;
    const size_t gr0 = (size_t)(b * SEQ + qg0) * DM + h * HD;
    const size_t gr1 = (size_t)(b * SEQ + qg1) * DM + h * HD;
#pragma unroll
    for (int nb = 0; nb < 8; nb++) {
        const int col = nb * 8 + tg * 2;
        *reinterpret_cast<uint32_t*>(outp + gr0 + col) =
            pack_h2(oacc[nb][0] * inv0, oacc[nb][1] * inv0);
        *reinterpret_cast<uint32_t*>(outp + gr1 + col) =
            pack_h2(oacc[nb][2] * inv1, oacc[nb][3] * inv1);
    }
}

// ---------------------------------------------------------------------------
extern "C" void kernel_launch(void* const* d_in, const int* in_sizes, int n_in,
                              void* d_out, int out_size)
{
    const float* x      = (const float*)d_in[0];
    const float* qkv_w  = (const float*)d_in[1];
    const float* qkv_b  = (const float*)d_in[2];
    const float* out_w  = (const float*)d_in[3];
    const float* out_b  = (const float*)d_in[4];
    float* out = (float*)d_out;

    __half *x16, *qkv16, *attn16, *w1t, *w2t;
    cudaGetSymbolAddress((void**)&x16, g_x16);
    cudaGetSymbolAddress((void**)&qkv16, g_qkv16);
    cudaGetSymbolAddress((void**)&attn16, g_attn16);
    cudaGetSymbolAddress((void**)&w1t, g_w1t);
    cudaGetSymbolAddress((void**)&w2t, g_w2t);

    cudaFuncSetAttribute(hgemm_bias<0>, cudaFuncAttributeMaxDynamicSharedMemorySize, GEMM_SMEM);
    cudaFuncSetAttribute(hgemm_bias<1>, cudaFuncAttributeMaxDynamicSharedMemorySize, GEMM_SMEM);
    cudaFuncSetAttribute(swa_h_kernel, cudaFuncAttributeMaxDynamicSharedMemorySize, ATT_SMEM);

    // single fused pre-pass (x cvt + both weight transposes)
    prepass_kernel<<<PRE_BLOCKS, 256>>>(x, qkv_w, out_w, x16, w1t, w2t);

    dim3 g1(NQKV / 128, MTOT / 128);
    hgemm_bias<1><<<g1, 128, GEMM_SMEM>>>(x16, w1t, qkv_b, qkv16, MTOT, NQKV, DM);

    dim3 ga(SEQ / 128, BATCH * NH);
    swa_h_kernel<<<ga, 256, ATT_SMEM>>>(qkv16, attn16);

    dim3 g2(DM / 128, MTOT / 128);
    hgemm_bias<0><<<g2, 128, GEMM_SMEM>>>(attn16, w2t, out_b, out, MTOT, DM, DM);
}